// round 1
// baseline (speedup 1.0000x reference)
#include <cuda_runtime.h>
#include <math.h>

// ---------------------------------------------------------------------------
// Problem constants (fixed by the dataset's setup_inputs)
// ---------------------------------------------------------------------------
#define MAXN 20000
#define MAXE 320000
#define MAXET (MAXE + MAXN)
#define H1 8
#define C1 32
#define F1 256   // H1*C1
#define F0 128   // dim_in
#define F2 64    // dim_out (heads=1)

// ---------------------------------------------------------------------------
// Scratch (allocation-free: __device__ globals)
// ---------------------------------------------------------------------------
__device__ float g_xl1[MAXN * F1];
__device__ float g_xr1[MAXN * F1];
__device__ float g_h1 [MAXN * F1];
__device__ float g_sc1[MAXET * H1];
__device__ float g_mx1[MAXN * H1];
__device__ float g_dn1[MAXN * H1];

__device__ float g_xl2[MAXN * F2];
__device__ float g_xr2[MAXN * F2];
__device__ float g_h2 [MAXN * F2];
__device__ float g_sc2[MAXET];
__device__ float g_mx2[MAXN];
__device__ float g_dn2[MAXN];

__device__ float g_mean[F2];
__device__ float g_rstd[F2];

// ---------------------------------------------------------------------------
// Helpers
// ---------------------------------------------------------------------------
__device__ __forceinline__ void atomicMaxF(float* addr, float v) {
    // int/uint monotonic trick; valid with -inf init
    if (v >= 0.f) atomicMax((int*)addr, __float_as_int(v));
    else          atomicMin((unsigned int*)addr, (unsigned int)__float_as_int(v));
}

__device__ __forceinline__ float warpSum(float v) {
    #pragma unroll
    for (int o = 16; o > 0; o >>= 1) v += __shfl_xor_sync(0xFFFFFFFFu, v, o);
    return v;
}
__device__ __forceinline__ float warpMax(float v) {
    #pragma unroll
    for (int o = 16; o > 0; o >>= 1) v = fmaxf(v, __shfl_xor_sync(0xFFFFFFFFu, v, o));
    return v;
}

// ---------------------------------------------------------------------------
// Simple tiled fp32 GEMM: C[M,Nc] = A[M,K] @ W[K,Nc]
// M multiple of 16 (20000), K,Nc multiples of 16.
// ---------------------------------------------------------------------------
__global__ void gemm_kernel(const float* __restrict__ A,
                            const float* __restrict__ W,
                            float* __restrict__ C,
                            int M, int K, int Nc) {
    __shared__ float As[16][16];
    __shared__ float Ws[16][17];
    int tx = threadIdx.x, ty = threadIdx.y;
    int row = blockIdx.y * 16 + ty;
    int col = blockIdx.x * 16 + tx;
    float acc = 0.f;
    for (int k0 = 0; k0 < K; k0 += 16) {
        As[ty][tx] = (row < M) ? A[row * K + k0 + tx] : 0.f;
        Ws[ty][tx] = W[(k0 + ty) * Nc + col];
        __syncthreads();
        #pragma unroll
        for (int kk = 0; kk < 16; kk++) acc += As[ty][kk] * Ws[kk][tx];
        __syncthreads();
    }
    if (row < M) C[row * Nc + col] = acc;
}

// ---------------------------------------------------------------------------
// Init
// ---------------------------------------------------------------------------
__global__ void init1_kernel(int N) {
    int i = blockIdx.x * blockDim.x + threadIdx.x;
    if (i < N * H1) { g_mx1[i] = -INFINITY; g_dn1[i] = 0.f; }
    if (i < N * F1) g_h1[i] = 0.f;
}
__global__ void init2_kernel(int N) {
    int i = blockIdx.x * blockDim.x + threadIdx.x;
    if (i < N) { g_mx2[i] = -INFINITY; g_dn2[i] = 0.f; }
    if (i < N * F2) g_h2[i] = 0.f;
}

// ---------------------------------------------------------------------------
// Layer-1 edge scoring: one warp per (edge, head); C1 == 32 lanes exactly.
// score[e,h] = sum_c att1[h,c] * leaky(xl[src,h,c] + xr[dst,h,c])
// ---------------------------------------------------------------------------
__global__ void score1_kernel(const int* __restrict__ src,
                              const int* __restrict__ dst,
                              const float* __restrict__ att1,
                              int E, int ET) {
    int e = blockIdx.x;
    if (e >= ET) return;
    int h = threadIdx.x >> 5, lane = threadIdx.x & 31;
    int s, d;
    if (e < E) { s = src[e]; d = dst[e]; } else { s = d = e - E; }
    float v = g_xl1[s * F1 + h * C1 + lane] + g_xr1[d * F1 + h * C1 + lane];
    v = (v > 0.f) ? v : 0.2f * v;
    float p = warpSum(v * att1[h * C1 + lane]);
    if (lane == 0) {
        g_sc1[e * H1 + h] = p;
        atomicMaxF(&g_mx1[d * H1 + h], p);
    }
}

// exp + denom accumulate: one thread per (edge, head)
__global__ void denom1_kernel(const int* __restrict__ src,
                              const int* __restrict__ dst,
                              int E, int ET) {
    int i = blockIdx.x * blockDim.x + threadIdx.x;
    if (i >= ET * H1) return;
    int e = i >> 3, h = i & 7;
    int d = (e < E) ? dst[e] : e - E;
    float ex = expf(g_sc1[i] - g_mx1[d * H1 + h]);
    g_sc1[i] = ex;
    atomicAdd(&g_dn1[d * H1 + h], ex);
}

// aggregation: one warp per (edge, head)
__global__ void agg1_kernel(const int* __restrict__ src,
                            const int* __restrict__ dst,
                            int E, int ET) {
    int e = blockIdx.x;
    if (e >= ET) return;
    int h = threadIdx.x >> 5, lane = threadIdx.x & 31;
    int s, d;
    if (e < E) { s = src[e]; d = dst[e]; } else { s = d = e - E; }
    float alpha = g_sc1[e * H1 + h] / (g_dn1[d * H1 + h] + 1e-16f);
    atomicAdd(&g_h1[d * F1 + h * C1 + lane],
              alpha * g_xl1[s * F1 + h * C1 + lane]);
}

// bias + elu
__global__ void biaselu_kernel(const float* __restrict__ b1, int N) {
    int i = blockIdx.x * blockDim.x + threadIdx.x;
    if (i >= N * F1) return;
    float v = g_h1[i] + b1[i & (F1 - 1)];
    g_h1[i] = (v > 0.f) ? v : (expf(v) - 1.f);
}

// ---------------------------------------------------------------------------
// Layer-2 edge scoring: one warp per edge, lane covers channels c and c+32.
// ---------------------------------------------------------------------------
__global__ void score2_kernel(const int* __restrict__ src,
                              const int* __restrict__ dst,
                              const float* __restrict__ att2,
                              int E, int ET) {
    int e = blockIdx.x * 4 + (threadIdx.x >> 5);
    if (e >= ET) return;
    int lane = threadIdx.x & 31;
    int s, d;
    if (e < E) { s = src[e]; d = dst[e]; } else { s = d = e - E; }
    float v0 = g_xl2[s * F2 + lane]      + g_xr2[d * F2 + lane];
    float v1 = g_xl2[s * F2 + 32 + lane] + g_xr2[d * F2 + 32 + lane];
    v0 = (v0 > 0.f) ? v0 : 0.2f * v0;
    v1 = (v1 > 0.f) ? v1 : 0.2f * v1;
    float p = warpSum(v0 * att2[lane] + v1 * att2[32 + lane]);
    if (lane == 0) {
        g_sc2[e] = p;
        atomicMaxF(&g_mx2[d], p);
    }
}

__global__ void denom2_kernel(const int* __restrict__ src,
                              const int* __restrict__ dst,
                              int E, int ET) {
    int e = blockIdx.x * blockDim.x + threadIdx.x;
    if (e >= ET) return;
    int d = (e < E) ? dst[e] : e - E;
    float ex = expf(g_sc2[e] - g_mx2[d]);
    g_sc2[e] = ex;
    atomicAdd(&g_dn2[d], ex);
}

__global__ void agg2_kernel(const int* __restrict__ src,
                            const int* __restrict__ dst,
                            int E, int ET) {
    int e = blockIdx.x * 4 + (threadIdx.x >> 5);
    if (e >= ET) return;
    int lane = threadIdx.x & 31;
    int s, d;
    if (e < E) { s = src[e]; d = dst[e]; } else { s = d = e - E; }
    float alpha = g_sc2[e] / (g_dn2[d] + 1e-16f);
    atomicAdd(&g_h2[d * F2 + lane],      alpha * g_xl2[s * F2 + lane]);
    atomicAdd(&g_h2[d * F2 + 32 + lane], alpha * g_xl2[s * F2 + 32 + lane]);
}

// ---------------------------------------------------------------------------
// InstanceNorm stats: one block per channel (64 blocks), double accumulation.
// NOTE: b2 cancels exactly under the mean subtraction, so it is skipped.
// ---------------------------------------------------------------------------
__global__ void stats_kernel(int N) {
    int c = blockIdx.x;
    __shared__ double ssum[256], ssq[256];
    double s = 0.0, q = 0.0;
    for (int i = threadIdx.x; i < N; i += blockDim.x) {
        double v = (double)g_h2[i * F2 + c];
        s += v; q += v * v;
    }
    ssum[threadIdx.x] = s; ssq[threadIdx.x] = q;
    __syncthreads();
    for (int o = 128; o > 0; o >>= 1) {
        if (threadIdx.x < o) {
            ssum[threadIdx.x] += ssum[threadIdx.x + o];
            ssq[threadIdx.x]  += ssq[threadIdx.x + o];
        }
        __syncthreads();
    }
    if (threadIdx.x == 0) {
        double mean = ssum[0] / N;
        double var  = ssq[0] / N - mean * mean;
        g_mean[c] = (float)mean;
        g_rstd[c] = (float)(1.0 / sqrt(var + 1e-5));
    }
}

// ---------------------------------------------------------------------------
// Normalize + log_softmax: one warp per node; lane covers c and c+32.
// out[0 : N*64)      = normalized h
// out[N*64 : 2*N*64) = log_softmax(h)
// ---------------------------------------------------------------------------
__global__ void finalize_kernel(const float* __restrict__ gamma,
                                const float* __restrict__ beta,
                                float* __restrict__ out, int N) {
    int node = blockIdx.x * 4 + (threadIdx.x >> 5);
    if (node >= N) return;
    int lane = threadIdx.x & 31;
    int c0 = lane, c1 = lane + 32;
    float y0 = (g_h2[node * F2 + c0] - g_mean[c0]) * g_rstd[c0] * gamma[c0] + beta[c0];
    float y1 = (g_h2[node * F2 + c1] - g_mean[c1]) * g_rstd[c1] * gamma[c1] + beta[c1];
    out[node * F2 + c0] = y0;
    out[node * F2 + c1] = y1;
    float m = warpMax(fmaxf(y0, y1));
    float ssum = warpSum(expf(y0 - m) + expf(y1 - m));
    float lse = m + logf(ssum);
    float* out2 = out + (size_t)N * F2;
    out2[node * F2 + c0] = y0 - lse;
    out2[node * F2 + c1] = y1 - lse;
}

// ---------------------------------------------------------------------------
// Launcher
// ---------------------------------------------------------------------------
extern "C" void kernel_launch(void* const* d_in, const int* in_sizes, int n_in,
                              void* d_out, int out_size) {
    const float* x     = (const float*)d_in[0];
    const float* Wl1   = (const float*)d_in[1];
    const float* Wr1   = (const float*)d_in[2];
    const float* att1  = (const float*)d_in[3];
    const float* b1    = (const float*)d_in[4];
    const float* Wl2   = (const float*)d_in[5];
    const float* Wr2   = (const float*)d_in[6];
    const float* att2  = (const float*)d_in[7];
    // d_in[8] = b2 : cancels under InstanceNorm, unused
    const float* gamma = (const float*)d_in[9];
    const float* beta  = (const float*)d_in[10];
    const int*   ei    = (const int*)d_in[11];

    int N = in_sizes[0] / F0;
    int E = in_sizes[11] / 2;
    int ET = E + N;
    const int* src = ei;
    const int* dst = ei + E;

    float *xl1, *xr1, *h1, *xl2, *xr2;
    cudaGetSymbolAddress((void**)&xl1, g_xl1);
    cudaGetSymbolAddress((void**)&xr1, g_xr1);
    cudaGetSymbolAddress((void**)&h1,  g_h1);
    cudaGetSymbolAddress((void**)&xl2, g_xl2);
    cudaGetSymbolAddress((void**)&xr2, g_xr2);

    dim3 tb(16, 16);

    // ---- Layer 1 GEMMs: xl1 = x@Wl1, xr1 = x@Wr1
    {
        dim3 grid(F1 / 16, (N + 15) / 16);
        gemm_kernel<<<grid, tb>>>(x, Wl1, xl1, N, F0, F1);
        gemm_kernel<<<grid, tb>>>(x, Wr1, xr1, N, F0, F1);
    }

    // ---- Layer 1 softmax/aggregate
    init1_kernel<<<(N * F1 + 255) / 256, 256>>>(N);
    score1_kernel<<<ET, 256>>>(src, dst, att1, E, ET);
    denom1_kernel<<<(ET * H1 + 255) / 256, 256>>>(src, dst, E, ET);
    agg1_kernel<<<ET, 256>>>(src, dst, E, ET);
    biaselu_kernel<<<(N * F1 + 255) / 256, 256>>>(b1, N);

    // ---- Layer 2 GEMMs: xl2 = h1@Wl2, xr2 = h1@Wr2
    {
        dim3 grid(F2 / 16, (N + 15) / 16);
        gemm_kernel<<<grid, tb>>>(h1, Wl2, xl2, N, F1, F2);
        gemm_kernel<<<grid, tb>>>(h1, Wr2, xr2, N, F1, F2);
    }

    // ---- Layer 2 softmax/aggregate
    init2_kernel<<<(N * F2 + 255) / 256, 256>>>(N);
    score2_kernel<<<(ET + 3) / 4, 128>>>(src, dst, att2, E, ET);
    denom2_kernel<<<(ET + 255) / 256, 256>>>(src, dst, E, ET);
    agg2_kernel<<<(ET + 3) / 4, 128>>>(src, dst, E, ET);

    // ---- InstanceNorm + log_softmax
    stats_kernel<<<F2, 256>>>(N);
    finalize_kernel<<<(N + 3) / 4, 128>>>(gamma, beta, (float*)d_out, N);
}

// round 2
// speedup vs baseline: 3.0506x; 3.0506x over previous
#include <cuda_runtime.h>
#include <math.h>

#define MAXN 20000
#define MAXE 320000
#define MAXET (MAXE + MAXN)
#define H1 8
#define C1 32
#define F1 256
#define F0 128
#define F2 64

// ---------------------------------------------------------------------------
// Scratch
// ---------------------------------------------------------------------------
__device__ float g_xl1[MAXN * F1];
__device__ float g_xr1[MAXN * F1];
__device__ float g_h1 [MAXN * F1];
__device__ float g_xl2[MAXN * F2];
__device__ float g_xr2[MAXN * F2];
__device__ float g_h2 [MAXN * F2];

__device__ int g_deg[MAXN];
__device__ int g_rowptr[MAXN + 1];
__device__ int g_cursor[MAXN];
__device__ int g_csrc[MAXET];

__device__ float g_mean[F2];
__device__ float g_rstd[F2];

// ---------------------------------------------------------------------------
// Helpers
// ---------------------------------------------------------------------------
__device__ __forceinline__ float warpSum(float v) {
    #pragma unroll
    for (int o = 16; o > 0; o >>= 1) v += __shfl_xor_sync(0xFFFFFFFFu, v, o);
    return v;
}
__device__ __forceinline__ float warpMax(float v) {
    #pragma unroll
    for (int o = 16; o > 0; o >>= 1) v = fmaxf(v, __shfl_xor_sync(0xFFFFFFFFu, v, o));
    return v;
}

// ---------------------------------------------------------------------------
// CSR build
// ---------------------------------------------------------------------------
__global__ void zero_deg_kernel(int N) {
    int i = blockIdx.x * blockDim.x + threadIdx.x;
    if (i < N) g_deg[i] = 0;
}

__global__ void hist_kernel(const int* __restrict__ dst, int E, int ET) {
    int i = blockIdx.x * blockDim.x + threadIdx.x;
    if (i >= ET) return;
    int d = (i < E) ? dst[i] : i - E;
    atomicAdd(&g_deg[d], 1);
}

// single-block scan over N (exclusive prefix)
__global__ void scan_kernel(int N) {
    __shared__ int sh[1024];
    __shared__ int carry;
    int tid = threadIdx.x;
    if (tid == 0) carry = 0;
    __syncthreads();
    for (int base = 0; base < N; base += 1024) {
        int i = base + tid;
        int v = (i < N) ? g_deg[i] : 0;
        sh[tid] = v;
        __syncthreads();
        #pragma unroll
        for (int o = 1; o < 1024; o <<= 1) {
            int t = (tid >= o) ? sh[tid - o] : 0;
            __syncthreads();
            sh[tid] += t;
            __syncthreads();
        }
        int excl = sh[tid] - v + carry;
        if (i < N) { g_rowptr[i] = excl; g_cursor[i] = excl; }
        __syncthreads();
        if (tid == 0) carry += sh[1023];
        __syncthreads();
    }
    if (tid == 0) g_rowptr[N] = carry;
}

__global__ void scatter_kernel(const int* __restrict__ src,
                               const int* __restrict__ dst, int E, int ET) {
    int i = blockIdx.x * blockDim.x + threadIdx.x;
    if (i >= ET) return;
    int s, d;
    if (i < E) { s = src[i]; d = dst[i]; } else { s = d = i - E; }
    int slot = atomicAdd(&g_cursor[d], 1);
    g_csrc[slot] = s;
}

// ---------------------------------------------------------------------------
// Register-blocked SGEMM: C[M,Nc] = A[M,K] @ B[K,Nc]
// BM=BN=64, BK=16, 256 threads, 4x4 outputs/thread. K,Nc multiples of 16/64.
// ---------------------------------------------------------------------------
__global__ void sgemm_kernel(const float* __restrict__ A,
                             const float* __restrict__ B,
                             float* __restrict__ C,
                             int M, int K, int Nc) {
    __shared__ float As[16][64];
    __shared__ float Bs[16][64];
    int tid = threadIdx.x;
    int tx = tid & 15, ty = tid >> 4;
    int row0 = blockIdx.y * 64, col0 = blockIdx.x * 64;

    int arow = tid >> 2;          // 0..63
    int acol = (tid & 3) * 4;     // 0,4,8,12
    int brow = tid >> 4;          // 0..15
    int bcol = (tid & 15) * 4;

    float acc[4][4] = {};

    for (int k0 = 0; k0 < K; k0 += 16) {
        float4 av;
        int gr = row0 + arow;
        if (gr < M) av = *(const float4*)&A[(size_t)gr * K + k0 + acol];
        else av = make_float4(0.f, 0.f, 0.f, 0.f);
        As[acol + 0][arow] = av.x;
        As[acol + 1][arow] = av.y;
        As[acol + 2][arow] = av.z;
        As[acol + 3][arow] = av.w;
        *(float4*)&Bs[brow][bcol] =
            *(const float4*)&B[(size_t)(k0 + brow) * Nc + col0 + bcol];
        __syncthreads();
        #pragma unroll
        for (int kk = 0; kk < 16; kk++) {
            float4 a = *(float4*)&As[kk][ty * 4];
            float4 b = *(float4*)&Bs[kk][tx * 4];
            acc[0][0] += a.x * b.x; acc[0][1] += a.x * b.y;
            acc[0][2] += a.x * b.z; acc[0][3] += a.x * b.w;
            acc[1][0] += a.y * b.x; acc[1][1] += a.y * b.y;
            acc[1][2] += a.y * b.z; acc[1][3] += a.y * b.w;
            acc[2][0] += a.z * b.x; acc[2][1] += a.z * b.y;
            acc[2][2] += a.z * b.z; acc[2][3] += a.z * b.w;
            acc[3][0] += a.w * b.x; acc[3][1] += a.w * b.y;
            acc[3][2] += a.w * b.z; acc[3][3] += a.w * b.w;
        }
        __syncthreads();
    }
    #pragma unroll
    for (int i = 0; i < 4; i++) {
        int gr = row0 + ty * 4 + i;
        if (gr < M) {
            float4 o = make_float4(acc[i][0], acc[i][1], acc[i][2], acc[i][3]);
            *(float4*)&C[(size_t)gr * Nc + col0 + tx * 4] = o;
        }
    }
}

// ---------------------------------------------------------------------------
// Fused GAT layer 1: block per node, warp h handles head h.
// Online softmax over CSR(dst) edges; epilogue = +b1, ELU. No atomics.
// ---------------------------------------------------------------------------
__global__ void gat1_node_kernel(const float* __restrict__ att1,
                                 const float* __restrict__ b1) {
    int d = blockIdx.x;
    int h = threadIdx.x >> 5, lane = threadIdx.x & 31;
    int off = h * C1 + lane;
    float a  = att1[off];
    float xr = g_xr1[d * F1 + off];
    int beg = g_rowptr[d], end = g_rowptr[d + 1];

    float m = -INFINITY, den = 0.f, acc = 0.f;

    int s = g_csrc[beg];
    float xv = g_xl1[s * F1 + off];
    for (int j = beg; j < end; j++) {
        float cur = xv;
        if (j + 1 < end) {
            int s2 = g_csrc[j + 1];
            xv = g_xl1[s2 * F1 + off];
        }
        float v = cur + xr;
        v = (v > 0.f) ? v : 0.2f * v;
        float p = warpSum(v * a);
        if (p > m) {
            float r = __expf(m - p);
            den *= r; acc *= r; m = p;
        }
        float w = __expf(p - m);
        den += w;
        acc += w * cur;
    }
    float out = acc / (den + 1e-16f) + b1[off];
    g_h1[d * F1 + off] = (out > 0.f) ? out : (__expf(out) - 1.f);
}

// ---------------------------------------------------------------------------
// Fused GAT layer 2: warp per node, lane covers channels c and c+32.
// ---------------------------------------------------------------------------
__global__ void gat2_node_kernel(const float* __restrict__ att2, int N) {
    int d = blockIdx.x * 4 + (threadIdx.x >> 5);
    if (d >= N) return;
    int lane = threadIdx.x & 31;
    float a0 = att2[lane], a1 = att2[32 + lane];
    float xr0 = g_xr2[d * F2 + lane];
    float xr1 = g_xr2[d * F2 + 32 + lane];
    int beg = g_rowptr[d], end = g_rowptr[d + 1];

    float m = -INFINITY, den = 0.f, acc0 = 0.f, acc1 = 0.f;

    int s = g_csrc[beg];
    float xv0 = g_xl2[s * F2 + lane];
    float xv1 = g_xl2[s * F2 + 32 + lane];
    for (int j = beg; j < end; j++) {
        float c0 = xv0, c1 = xv1;
        if (j + 1 < end) {
            int s2 = g_csrc[j + 1];
            xv0 = g_xl2[s2 * F2 + lane];
            xv1 = g_xl2[s2 * F2 + 32 + lane];
        }
        float v0 = c0 + xr0; v0 = (v0 > 0.f) ? v0 : 0.2f * v0;
        float v1 = c1 + xr1; v1 = (v1 > 0.f) ? v1 : 0.2f * v1;
        float p = warpSum(v0 * a0 + v1 * a1);
        if (p > m) {
            float r = __expf(m - p);
            den *= r; acc0 *= r; acc1 *= r; m = p;
        }
        float w = __expf(p - m);
        den += w;
        acc0 += w * c0;
        acc1 += w * c1;
    }
    float inv = 1.f / (den + 1e-16f);
    g_h2[d * F2 + lane]      = acc0 * inv;   // b2 cancels in InstanceNorm
    g_h2[d * F2 + 32 + lane] = acc1 * inv;
}

// ---------------------------------------------------------------------------
// InstanceNorm stats (block per channel)
// ---------------------------------------------------------------------------
__global__ void stats_kernel(int N) {
    int c = blockIdx.x;
    __shared__ double ssum[256], ssq[256];
    double s = 0.0, q = 0.0;
    for (int i = threadIdx.x; i < N; i += blockDim.x) {
        double v = (double)g_h2[i * F2 + c];
        s += v; q += v * v;
    }
    ssum[threadIdx.x] = s; ssq[threadIdx.x] = q;
    __syncthreads();
    for (int o = 128; o > 0; o >>= 1) {
        if (threadIdx.x < o) {
            ssum[threadIdx.x] += ssum[threadIdx.x + o];
            ssq[threadIdx.x]  += ssq[threadIdx.x + o];
        }
        __syncthreads();
    }
    if (threadIdx.x == 0) {
        double mean = ssum[0] / N;
        double var  = ssq[0] / N - mean * mean;
        g_mean[c] = (float)mean;
        g_rstd[c] = (float)(1.0 / sqrt(var + 1e-5));
    }
}

// ---------------------------------------------------------------------------
// Normalize + log_softmax
// ---------------------------------------------------------------------------
__global__ void finalize_kernel(const float* __restrict__ gamma,
                                const float* __restrict__ beta,
                                float* __restrict__ out, int N) {
    int node = blockIdx.x * 4 + (threadIdx.x >> 5);
    if (node >= N) return;
    int lane = threadIdx.x & 31;
    int c0 = lane, c1 = lane + 32;
    float y0 = (g_h2[node * F2 + c0] - g_mean[c0]) * g_rstd[c0] * gamma[c0] + beta[c0];
    float y1 = (g_h2[node * F2 + c1] - g_mean[c1]) * g_rstd[c1] * gamma[c1] + beta[c1];
    out[node * F2 + c0] = y0;
    out[node * F2 + c1] = y1;
    float m = warpMax(fmaxf(y0, y1));
    float ssum = warpSum(expf(y0 - m) + expf(y1 - m));
    float lse = m + logf(ssum);
    float* out2 = out + (size_t)N * F2;
    out2[node * F2 + c0] = y0 - lse;
    out2[node * F2 + c1] = y1 - lse;
}

// ---------------------------------------------------------------------------
// Launcher
// ---------------------------------------------------------------------------
extern "C" void kernel_launch(void* const* d_in, const int* in_sizes, int n_in,
                              void* d_out, int out_size) {
    const float* x     = (const float*)d_in[0];
    const float* Wl1   = (const float*)d_in[1];
    const float* Wr1   = (const float*)d_in[2];
    const float* att1  = (const float*)d_in[3];
    const float* b1    = (const float*)d_in[4];
    const float* Wl2   = (const float*)d_in[5];
    const float* Wr2   = (const float*)d_in[6];
    const float* att2  = (const float*)d_in[7];
    const float* gamma = (const float*)d_in[9];
    const float* beta  = (const float*)d_in[10];
    const int*   ei    = (const int*)d_in[11];

    int N = in_sizes[0] / F0;
    int E = in_sizes[11] / 2;
    int ET = E + N;
    const int* src = ei;
    const int* dst = ei + E;

    float *xl1, *xr1, *h1, *xl2, *xr2;
    cudaGetSymbolAddress((void**)&xl1, g_xl1);
    cudaGetSymbolAddress((void**)&xr1, g_xr1);
    cudaGetSymbolAddress((void**)&h1,  g_h1);
    cudaGetSymbolAddress((void**)&xl2, g_xl2);
    cudaGetSymbolAddress((void**)&xr2, g_xr2);

    // CSR build
    zero_deg_kernel<<<(N + 255) / 256, 256>>>(N);
    hist_kernel<<<(ET + 255) / 256, 256>>>(dst, E, ET);
    scan_kernel<<<1, 1024>>>(N);
    scatter_kernel<<<(ET + 255) / 256, 256>>>(src, dst, E, ET);

    // Layer 1 GEMMs
    {
        dim3 grid(F1 / 64, (N + 63) / 64);
        sgemm_kernel<<<grid, 256>>>(x, Wl1, xl1, N, F0, F1);
        sgemm_kernel<<<grid, 256>>>(x, Wr1, xr1, N, F0, F1);
    }
    // Fused layer-1 softmax+aggregate+bias+ELU
    gat1_node_kernel<<<N, 256>>>(att1, b1);

    // Layer 2 GEMMs
    {
        dim3 grid(F2 / 64, (N + 63) / 64);
        sgemm_kernel<<<grid, 256>>>(h1, Wl2, xl2, N, F1, F2);
        sgemm_kernel<<<grid, 256>>>(h1, Wr2, xr2, N, F1, F2);
    }
    // Fused layer-2 softmax+aggregate
    gat2_node_kernel<<<(N + 3) / 4, 128>>>(att2, N);

    // InstanceNorm + log_softmax
    stats_kernel<<<F2, 256>>>(N);
    finalize_kernel<<<(N + 3) / 4, 128>>>(gamma, beta, (float*)d_out, N);
}

// round 3
// speedup vs baseline: 3.6006x; 1.1803x over previous
#include <cuda_runtime.h>
#include <math.h>

#define MAXN 20000
#define MAXE 320000
#define MAXET (MAXE + MAXN)
#define H1 8
#define C1 32
#define F1 256
#define F0 128
#define F2 64

// ---------------------------------------------------------------------------
// Scratch
// ---------------------------------------------------------------------------
__device__ float g_xl1[MAXN * F1];
__device__ float g_xr1[MAXN * F1];
__device__ float g_h1 [MAXN * F1];
__device__ float g_xl2[MAXN * F2];
__device__ float g_xr2[MAXN * F2];
__device__ float g_h2 [MAXN * F2];

__device__ int g_deg[MAXN];
__device__ int g_rowptr[MAXN + 1];
__device__ int g_cursor[MAXN];
__device__ int g_csrc[MAXET];

__device__ float g_mean[F2];
__device__ float g_rstd[F2];

// ---------------------------------------------------------------------------
// Helpers
// ---------------------------------------------------------------------------
__device__ __forceinline__ float warpSum(float v) {
    #pragma unroll
    for (int o = 16; o > 0; o >>= 1) v += __shfl_xor_sync(0xFFFFFFFFu, v, o);
    return v;
}
__device__ __forceinline__ float warpMax(float v) {
    #pragma unroll
    for (int o = 16; o > 0; o >>= 1) v = fmaxf(v, __shfl_xor_sync(0xFFFFFFFFu, v, o));
    return v;
}
__device__ __forceinline__ unsigned f2tf32(float x) {
    unsigned u;
    asm("cvt.rna.tf32.f32 %0, %1;" : "=r"(u) : "f"(x));
    return u;
}

// ---------------------------------------------------------------------------
// CSR build
// ---------------------------------------------------------------------------
__global__ void zero_deg_kernel(int N) {
    int i = blockIdx.x * blockDim.x + threadIdx.x;
    if (i < N) g_deg[i] = 0;
}

__global__ void hist_kernel(const int* __restrict__ dst, int E, int ET) {
    int i = blockIdx.x * blockDim.x + threadIdx.x;
    if (i >= ET) return;
    int d = (i < E) ? dst[i] : i - E;
    atomicAdd(&g_deg[d], 1);
}

// Single-block chunked exclusive scan: 1024 threads x CHUNK nodes each.
#define SCAN_CHUNK 20
__global__ void scan_kernel(int N) {
    __shared__ int sh[1024];
    int tid = threadIdx.x;
    int start = tid * SCAN_CHUNK;
    int cnt = N - start;
    if (cnt < 0) cnt = 0;
    if (cnt > SCAN_CHUNK) cnt = SCAN_CHUNK;
    int vals[SCAN_CHUNK];
    int sum = 0;
    for (int i = 0; i < cnt; i++) { vals[i] = g_deg[start + i]; sum += vals[i]; }
    sh[tid] = sum;
    __syncthreads();
    #pragma unroll
    for (int o = 1; o < 1024; o <<= 1) {
        int t = (tid >= o) ? sh[tid - o] : 0;
        __syncthreads();
        sh[tid] += t;
        __syncthreads();
    }
    int run = sh[tid] - sum;
    for (int i = 0; i < cnt; i++) {
        g_rowptr[start + i] = run;
        g_cursor[start + i] = run;
        run += vals[i];
    }
    if (tid == 1023) g_rowptr[N] = sh[1023];
}

__global__ void scatter_kernel(const int* __restrict__ src,
                               const int* __restrict__ dst, int E, int ET) {
    int i = blockIdx.x * blockDim.x + threadIdx.x;
    if (i >= ET) return;
    int s, d;
    if (i < E) { s = src[i]; d = dst[i]; } else { s = d = i - E; }
    int slot = atomicAdd(&g_cursor[d], 1);
    g_csrc[slot] = s;
}

// ---------------------------------------------------------------------------
// TF32 tensor-core GEMM: C[M,Nc] = A[M,K] @ B[K,Nc]
// BM=BN=64, BK=16, 128 threads (4 warps, 2x2), warp tile 32x32.
// K % 16 == 0, Nc % 64 == 0. Inputs rounded to tf32 at smem fill.
// ---------------------------------------------------------------------------
#define PADA 20
#define PADB 72
__global__ void mma_gemm_kernel(const float* __restrict__ A,
                                const float* __restrict__ B,
                                float* __restrict__ C,
                                int M, int K, int Nc) {
    __shared__ float As[64][PADA];   // [m][k], tf32 bit patterns
    __shared__ float Bs[16][PADB];   // [k][n]
    int tid = threadIdx.x;
    int lane = tid & 31, warp = tid >> 5;
    int wm = warp >> 1, wn = warp & 1;
    int g = lane >> 2, tg = lane & 3;
    int row0 = blockIdx.y * 64, col0 = blockIdx.x * 64;

    float acc[2][4][4];
    #pragma unroll
    for (int i = 0; i < 2; i++)
        #pragma unroll
        for (int j = 0; j < 4; j++)
            #pragma unroll
            for (int k = 0; k < 4; k++) acc[i][j][k] = 0.f;

    for (int k0 = 0; k0 < K; k0 += 16) {
        // Load A tile (64x16): 256 float4
        #pragma unroll
        for (int f = tid; f < 256; f += 128) {
            int r = f >> 2, c4 = (f & 3) * 4;
            float4 v = make_float4(0.f, 0.f, 0.f, 0.f);
            int gr = row0 + r;
            if (gr < M) v = *(const float4*)&A[(size_t)gr * K + k0 + c4];
            As[r][c4 + 0] = __uint_as_float(f2tf32(v.x));
            As[r][c4 + 1] = __uint_as_float(f2tf32(v.y));
            As[r][c4 + 2] = __uint_as_float(f2tf32(v.z));
            As[r][c4 + 3] = __uint_as_float(f2tf32(v.w));
        }
        // Load B tile (16x64): 256 float4
        #pragma unroll
        for (int f = tid; f < 256; f += 128) {
            int r = f >> 4, c4 = (f & 15) * 4;
            float4 v = *(const float4*)&B[(size_t)(k0 + r) * Nc + col0 + c4];
            Bs[r][c4 + 0] = __uint_as_float(f2tf32(v.x));
            Bs[r][c4 + 1] = __uint_as_float(f2tf32(v.y));
            Bs[r][c4 + 2] = __uint_as_float(f2tf32(v.z));
            Bs[r][c4 + 3] = __uint_as_float(f2tf32(v.w));
        }
        __syncthreads();
        #pragma unroll
        for (int kk = 0; kk < 16; kk += 8) {
            unsigned a[2][4], b[4][2];
            #pragma unroll
            for (int mt = 0; mt < 2; mt++) {
                int r = wm * 32 + mt * 16;
                a[mt][0] = __float_as_uint(As[r + g][kk + tg]);
                a[mt][1] = __float_as_uint(As[r + g + 8][kk + tg]);
                a[mt][2] = __float_as_uint(As[r + g][kk + tg + 4]);
                a[mt][3] = __float_as_uint(As[r + g + 8][kk + tg + 4]);
            }
            #pragma unroll
            for (int nt = 0; nt < 4; nt++) {
                int c = wn * 32 + nt * 8 + g;
                b[nt][0] = __float_as_uint(Bs[kk + tg][c]);
                b[nt][1] = __float_as_uint(Bs[kk + tg + 4][c]);
            }
            #pragma unroll
            for (int mt = 0; mt < 2; mt++)
                #pragma unroll
                for (int nt = 0; nt < 4; nt++) {
                    asm volatile(
                        "mma.sync.aligned.m16n8k8.row.col.f32.tf32.tf32.f32 "
                        "{%0,%1,%2,%3}, {%4,%5,%6,%7}, {%8,%9}, {%0,%1,%2,%3};\n"
                        : "+f"(acc[mt][nt][0]), "+f"(acc[mt][nt][1]),
                          "+f"(acc[mt][nt][2]), "+f"(acc[mt][nt][3])
                        : "r"(a[mt][0]), "r"(a[mt][1]), "r"(a[mt][2]), "r"(a[mt][3]),
                          "r"(b[nt][0]), "r"(b[nt][1]));
                }
        }
        __syncthreads();
    }
    // Epilogue
    #pragma unroll
    for (int mt = 0; mt < 2; mt++) {
        int rbase = row0 + wm * 32 + mt * 16;
        #pragma unroll
        for (int nt = 0; nt < 4; nt++) {
            int c = col0 + wn * 32 + nt * 8 + tg * 2;
            int r = rbase + g;
            if (r < M) {
                float2 o = make_float2(acc[mt][nt][0], acc[mt][nt][1]);
                *(float2*)&C[(size_t)r * Nc + c] = o;
            }
            r = rbase + g + 8;
            if (r < M) {
                float2 o = make_float2(acc[mt][nt][2], acc[mt][nt][3]);
                *(float2*)&C[(size_t)r * Nc + c] = o;
            }
        }
    }
}

// ---------------------------------------------------------------------------
// Fused GAT layer 1: block per node, warp h = head h.
// Online softmax, 2-edge interleaved chains for ILP. Epilogue: +b1, ELU.
// ---------------------------------------------------------------------------
__global__ void gat1_node_kernel(const float* __restrict__ att1,
                                 const float* __restrict__ b1) {
    int d = blockIdx.x;
    int h = threadIdx.x >> 5, lane = threadIdx.x & 31;
    int off = h * C1 + lane;
    float a  = att1[off];
    float xr = g_xr1[d * F1 + off];
    int beg = g_rowptr[d], end = g_rowptr[d + 1];

    float m0 = -INFINITY, den0 = 0.f, acc0 = 0.f;
    float m1 = -INFINITY, den1 = 0.f, acc1 = 0.f;

    float xa = g_xl1[g_csrc[beg] * F1 + off];
    float xb = (beg + 1 < end) ? g_xl1[g_csrc[beg + 1] * F1 + off] : 0.f;

    int j = beg;
    for (; j + 1 < end; j += 2) {
        float c0 = xa, c1 = xb;
        if (j + 2 < end) xa = g_xl1[g_csrc[j + 2] * F1 + off];
        if (j + 3 < end) xb = g_xl1[g_csrc[j + 3] * F1 + off];
        float v0 = c0 + xr; v0 = (v0 > 0.f) ? v0 : 0.2f * v0;
        float v1 = c1 + xr; v1 = (v1 > 0.f) ? v1 : 0.2f * v1;
        float p0 = warpSum(v0 * a);
        float p1 = warpSum(v1 * a);
        if (p0 > m0) { float r = __expf(m0 - p0); den0 *= r; acc0 *= r; m0 = p0; }
        float w0 = __expf(p0 - m0);
        den0 += w0; acc0 += w0 * c0;
        if (p1 > m1) { float r = __expf(m1 - p1); den1 *= r; acc1 *= r; m1 = p1; }
        float w1 = __expf(p1 - m1);
        den1 += w1; acc1 += w1 * c1;
    }
    if (j < end) {
        float v0 = xa + xr; v0 = (v0 > 0.f) ? v0 : 0.2f * v0;
        float p0 = warpSum(v0 * a);
        if (p0 > m0) { float r = __expf(m0 - p0); den0 *= r; acc0 *= r; m0 = p0; }
        float w0 = __expf(p0 - m0);
        den0 += w0; acc0 += w0 * xa;
    }
    float m = fmaxf(m0, m1);
    float e0 = __expf(m0 - m), e1 = (m1 == -INFINITY) ? 0.f : __expf(m1 - m);
    float den = den0 * e0 + den1 * e1;
    float acc = acc0 * e0 + acc1 * e1;
    float out = acc / (den + 1e-16f) + b1[off];
    g_h1[d * F1 + off] = (out > 0.f) ? out : (__expf(out) - 1.f);
}

// ---------------------------------------------------------------------------
// Fused GAT layer 2: warp per node, lane covers channels c and c+32.
// 2-edge interleaved chains.
// ---------------------------------------------------------------------------
__global__ void gat2_node_kernel(const float* __restrict__ att2, int N) {
    int d = blockIdx.x * 4 + (threadIdx.x >> 5);
    if (d >= N) return;
    int lane = threadIdx.x & 31;
    float a0 = att2[lane], a1 = att2[32 + lane];
    float xr0 = g_xr2[d * F2 + lane];
    float xr1 = g_xr2[d * F2 + 32 + lane];
    int beg = g_rowptr[d], end = g_rowptr[d + 1];

    float mA = -INFINITY, denA = 0.f, accA0 = 0.f, accA1 = 0.f;
    float mB = -INFINITY, denB = 0.f, accB0 = 0.f, accB1 = 0.f;

    int s0 = g_csrc[beg];
    float xa0 = g_xl2[s0 * F2 + lane];
    float xa1 = g_xl2[s0 * F2 + 32 + lane];
    float xb0 = 0.f, xb1 = 0.f;
    if (beg + 1 < end) {
        int s1 = g_csrc[beg + 1];
        xb0 = g_xl2[s1 * F2 + lane];
        xb1 = g_xl2[s1 * F2 + 32 + lane];
    }

    int j = beg;
    for (; j + 1 < end; j += 2) {
        float cA0 = xa0, cA1 = xa1, cB0 = xb0, cB1 = xb1;
        if (j + 2 < end) {
            int s = g_csrc[j + 2];
            xa0 = g_xl2[s * F2 + lane];
            xa1 = g_xl2[s * F2 + 32 + lane];
        }
        if (j + 3 < end) {
            int s = g_csrc[j + 3];
            xb0 = g_xl2[s * F2 + lane];
            xb1 = g_xl2[s * F2 + 32 + lane];
        }
        float vA0 = cA0 + xr0; vA0 = (vA0 > 0.f) ? vA0 : 0.2f * vA0;
        float vA1 = cA1 + xr1; vA1 = (vA1 > 0.f) ? vA1 : 0.2f * vA1;
        float vB0 = cB0 + xr0; vB0 = (vB0 > 0.f) ? vB0 : 0.2f * vB0;
        float vB1 = cB1 + xr1; vB1 = (vB1 > 0.f) ? vB1 : 0.2f * vB1;
        float pA = warpSum(vA0 * a0 + vA1 * a1);
        float pB = warpSum(vB0 * a0 + vB1 * a1);
        if (pA > mA) { float r = __expf(mA - pA); denA *= r; accA0 *= r; accA1 *= r; mA = pA; }
        float wA = __expf(pA - mA);
        denA += wA; accA0 += wA * cA0; accA1 += wA * cA1;
        if (pB > mB) { float r = __expf(mB - pB); denB *= r; accB0 *= r; accB1 *= r; mB = pB; }
        float wB = __expf(pB - mB);
        denB += wB; accB0 += wB * cB0; accB1 += wB * cB1;
    }
    if (j < end) {
        float vA0 = xa0 + xr0; vA0 = (vA0 > 0.f) ? vA0 : 0.2f * vA0;
        float vA1 = xa1 + xr1; vA1 = (vA1 > 0.f) ? vA1 : 0.2f * vA1;
        float pA = warpSum(vA0 * a0 + vA1 * a1);
        if (pA > mA) { float r = __expf(mA - pA); denA *= r; accA0 *= r; accA1 *= r; mA = pA; }
        float wA = __expf(pA - mA);
        denA += wA; accA0 += wA * xa0; accA1 += wA * xa1;
    }
    float m = fmaxf(mA, mB);
    float eA = __expf(mA - m), eB = (mB == -INFINITY) ? 0.f : __expf(mB - m);
    float den = denA * eA + denB * eB;
    float inv = 1.f / (den + 1e-16f);
    g_h2[d * F2 + lane]      = (accA0 * eA + accB0 * eB) * inv;
    g_h2[d * F2 + 32 + lane] = (accA1 * eA + accB1 * eB) * inv;
}

// ---------------------------------------------------------------------------
// InstanceNorm stats (block per channel)
// ---------------------------------------------------------------------------
__global__ void stats_kernel(int N) {
    int c = blockIdx.x;
    __shared__ double ssum[256], ssq[256];
    double s = 0.0, q = 0.0;
    for (int i = threadIdx.x; i < N; i += blockDim.x) {
        double v = (double)g_h2[i * F2 + c];
        s += v; q += v * v;
    }
    ssum[threadIdx.x] = s; ssq[threadIdx.x] = q;
    __syncthreads();
    for (int o = 128; o > 0; o >>= 1) {
        if (threadIdx.x < o) {
            ssum[threadIdx.x] += ssum[threadIdx.x + o];
            ssq[threadIdx.x]  += ssq[threadIdx.x + o];
        }
        __syncthreads();
    }
    if (threadIdx.x == 0) {
        double mean = ssum[0] / N;
        double var  = ssq[0] / N - mean * mean;
        g_mean[c] = (float)mean;
        g_rstd[c] = (float)(1.0 / sqrt(var + 1e-5));
    }
}

// ---------------------------------------------------------------------------
// Normalize + log_softmax
// ---------------------------------------------------------------------------
__global__ void finalize_kernel(const float* __restrict__ gamma,
                                const float* __restrict__ beta,
                                float* __restrict__ out, int N) {
    int node = blockIdx.x * 4 + (threadIdx.x >> 5);
    if (node >= N) return;
    int lane = threadIdx.x & 31;
    int c0 = lane, c1 = lane + 32;
    float y0 = (g_h2[node * F2 + c0] - g_mean[c0]) * g_rstd[c0] * gamma[c0] + beta[c0];
    float y1 = (g_h2[node * F2 + c1] - g_mean[c1]) * g_rstd[c1] * gamma[c1] + beta[c1];
    out[node * F2 + c0] = y0;
    out[node * F2 + c1] = y1;
    float m = warpMax(fmaxf(y0, y1));
    float ssum = warpSum(expf(y0 - m) + expf(y1 - m));
    float lse = m + logf(ssum);
    float* out2 = out + (size_t)N * F2;
    out2[node * F2 + c0] = y0 - lse;
    out2[node * F2 + c1] = y1 - lse;
}

// ---------------------------------------------------------------------------
// Launcher
// ---------------------------------------------------------------------------
extern "C" void kernel_launch(void* const* d_in, const int* in_sizes, int n_in,
                              void* d_out, int out_size) {
    const float* x     = (const float*)d_in[0];
    const float* Wl1   = (const float*)d_in[1];
    const float* Wr1   = (const float*)d_in[2];
    const float* att1  = (const float*)d_in[3];
    const float* b1    = (const float*)d_in[4];
    const float* Wl2   = (const float*)d_in[5];
    const float* Wr2   = (const float*)d_in[6];
    const float* att2  = (const float*)d_in[7];
    const float* gamma = (const float*)d_in[9];
    const float* beta  = (const float*)d_in[10];
    const int*   ei    = (const int*)d_in[11];

    int N = in_sizes[0] / F0;
    int E = in_sizes[11] / 2;
    int ET = E + N;
    const int* src = ei;
    const int* dst = ei + E;

    float *xl1, *xr1, *h1, *xl2, *xr2;
    cudaGetSymbolAddress((void**)&xl1, g_xl1);
    cudaGetSymbolAddress((void**)&xr1, g_xr1);
    cudaGetSymbolAddress((void**)&h1,  g_h1);
    cudaGetSymbolAddress((void**)&xl2, g_xl2);
    cudaGetSymbolAddress((void**)&xr2, g_xr2);

    // CSR build
    zero_deg_kernel<<<(N + 255) / 256, 256>>>(N);
    hist_kernel<<<(ET + 255) / 256, 256>>>(dst, E, ET);
    scan_kernel<<<1, 1024>>>(N);
    scatter_kernel<<<(ET + 255) / 256, 256>>>(src, dst, E, ET);

    // Layer 1 GEMMs (TF32 tensor cores)
    {
        dim3 grid(F1 / 64, (N + 63) / 64);
        mma_gemm_kernel<<<grid, 128>>>(x, Wl1, xl1, N, F0, F1);
        mma_gemm_kernel<<<grid, 128>>>(x, Wr1, xr1, N, F0, F1);
    }
    gat1_node_kernel<<<N, 256>>>(att1, b1);

    // Layer 2 GEMMs
    {
        dim3 grid(F2 / 64, (N + 63) / 64);
        mma_gemm_kernel<<<grid, 128>>>(h1, Wl2, xl2, N, F1, F2);
        mma_gemm_kernel<<<grid, 128>>>(h1, Wr2, xr2, N, F1, F2);
    }
    gat2_node_kernel<<<(N + 3) / 4, 128>>>(att2, N);

    // InstanceNorm + log_softmax
    stats_kernel<<<F2, 256>>>(N);
    finalize_kernel<<<(N + 3) / 4, 128>>>(gamma, beta, (float*)d_out, N);
}

// round 5
// speedup vs baseline: 4.2182x; 1.1715x over previous
#include <cuda_runtime.h>
#include <math.h>

#define MAXN 20000
#define MAXE 320000
#define MAXET (MAXE + MAXN)
#define H1 8
#define CH1 32
#define F1 256
#define F0 128
#define F2 64

// ---------------------------------------------------------------------------
// Scratch
// ---------------------------------------------------------------------------
__device__ float g_xl1[MAXN * F1];
__device__ float g_xr1[MAXN * F1];
__device__ float g_h1 [MAXN * F1];
__device__ float g_xl2[MAXN * F2];
__device__ float g_xr2[MAXN * F2];
__device__ float g_h2 [MAXN * F2];

__device__ int g_deg[MAXN];
__device__ int g_rowptr[MAXN + 1];
__device__ int g_cursor[MAXN];
__device__ int g_csrc[MAXET];

__device__ float g_mean[F2];
__device__ float g_rstd[F2];

// ---------------------------------------------------------------------------
// Helpers
// ---------------------------------------------------------------------------
__device__ __forceinline__ float warpSum(float v) {
    #pragma unroll
    for (int o = 16; o > 0; o >>= 1) v += __shfl_xor_sync(0xFFFFFFFFu, v, o);
    return v;
}
__device__ __forceinline__ float warpMax(float v) {
    #pragma unroll
    for (int o = 16; o > 0; o >>= 1) v = fmaxf(v, __shfl_xor_sync(0xFFFFFFFFu, v, o));
    return v;
}
__device__ __forceinline__ float f2tf32f(float x) {
    unsigned u;
    asm("cvt.rna.tf32.f32 %0, %1;" : "=r"(u) : "f"(x));
    return __uint_as_float(u);
}
__device__ __forceinline__ float leaky(float v) { return fmaxf(v, 0.2f * v); }

// ---------------------------------------------------------------------------
// CSR build
// ---------------------------------------------------------------------------
__global__ void zero_deg_kernel(int nN) {
    int i = blockIdx.x * blockDim.x + threadIdx.x;
    if (i < nN) g_deg[i] = 0;
}

__global__ void hist_kernel(const int* __restrict__ dst, int nE, int nET) {
    int i = blockIdx.x * blockDim.x + threadIdx.x;
    if (i >= nET) return;
    int d = (i < nE) ? dst[i] : i - nE;
    atomicAdd(&g_deg[d], 1);
}

#define SCAN_CHUNK 20
__global__ void scan_kernel(int nN) {
    __shared__ int sh[1024];
    int tid = threadIdx.x;
    int start = tid * SCAN_CHUNK;
    int cnt = nN - start;
    if (cnt < 0) cnt = 0;
    if (cnt > SCAN_CHUNK) cnt = SCAN_CHUNK;
    int vals[SCAN_CHUNK];
    int sum = 0;
    for (int i = 0; i < cnt; i++) { vals[i] = g_deg[start + i]; sum += vals[i]; }
    sh[tid] = sum;
    __syncthreads();
    #pragma unroll
    for (int o = 1; o < 1024; o <<= 1) {
        int t = (tid >= o) ? sh[tid - o] : 0;
        __syncthreads();
        sh[tid] += t;
        __syncthreads();
    }
    int run = sh[tid] - sum;
    for (int i = 0; i < cnt; i++) {
        g_rowptr[start + i] = run;
        g_cursor[start + i] = run;
        run += vals[i];
    }
    if (tid == 1023) g_rowptr[nN] = sh[1023];
}

__global__ void scatter_kernel(const int* __restrict__ src,
                               const int* __restrict__ dst, int nE, int nET) {
    int i = blockIdx.x * blockDim.x + threadIdx.x;
    if (i >= nET) return;
    int s, d;
    if (i < nE) { s = src[i]; d = dst[i]; } else { s = d = i - nE; }
    int slot = atomicAdd(&g_cursor[d], 1);
    g_csrc[slot] = s;
}

// ---------------------------------------------------------------------------
// Pipelined TF32 GEMM: BM=128, BN=64, BK=16, 256 threads (8 warps, 4x2).
// blockIdx.z selects (Bl,Cl) or (Br,Cr). Double-buffered smem, reg prefetch.
// ---------------------------------------------------------------------------
#define PADA 20
#define PADB 72
__global__ void mma_gemm2_kernel(const float* __restrict__ Amat,
                                 const float* __restrict__ Bl,
                                 const float* __restrict__ Br,
                                 float* __restrict__ outL,
                                 float* __restrict__ outR,
                                 int Mdim, int Kdim, int Ndim) {
    const float* Bmat = blockIdx.z ? Br : Bl;
    float*       Cmat = blockIdx.z ? outR : outL;
    __shared__ __align__(16) float As[2][128][PADA];
    __shared__ __align__(16) float Bs[2][16][PADB];
    int tid = threadIdx.x;
    int lane = tid & 31, warp = tid >> 5;
    int wm = warp >> 1, wn = warp & 1;           // 4 x 2 warps
    int g = lane >> 2, tg = lane & 3;
    int row0 = blockIdx.y * 128, col0 = blockIdx.x * 64;

    int ar0 = tid >> 2, ac = (tid & 3) * 4;
    int br = tid >> 4, bc = (tid & 15) * 4;

    float4 ra[2], rb;

    float acc[2][4][4];
    #pragma unroll
    for (int i = 0; i < 2; i++)
        #pragma unroll
        for (int j = 0; j < 4; j++)
            #pragma unroll
            for (int k = 0; k < 4; k++) acc[i][j][k] = 0.f;

    int nit = Kdim / 16;

    #pragma unroll
    for (int i = 0; i < 2; i++) {
        int gr = row0 + ar0 + i * 64;
        ra[i] = (gr < Mdim) ? *(const float4*)&Amat[(size_t)gr * Kdim + ac]
                            : make_float4(0.f, 0.f, 0.f, 0.f);
    }
    rb = *(const float4*)&Bmat[(size_t)br * Ndim + col0 + bc];
    #pragma unroll
    for (int i = 0; i < 2; i++) {
        int r = ar0 + i * 64;
        As[0][r][ac + 0] = f2tf32f(ra[i].x);
        As[0][r][ac + 1] = f2tf32f(ra[i].y);
        As[0][r][ac + 2] = f2tf32f(ra[i].z);
        As[0][r][ac + 3] = f2tf32f(ra[i].w);
    }
    Bs[0][br][bc + 0] = f2tf32f(rb.x);
    Bs[0][br][bc + 1] = f2tf32f(rb.y);
    Bs[0][br][bc + 2] = f2tf32f(rb.z);
    Bs[0][br][bc + 3] = f2tf32f(rb.w);
    __syncthreads();

    for (int it = 0; it < nit; it++) {
        int k0n = (it + 1) * 16;
        bool more = (it + 1) < nit;
        if (more) {
            #pragma unroll
            for (int i = 0; i < 2; i++) {
                int gr = row0 + ar0 + i * 64;
                ra[i] = (gr < Mdim) ? *(const float4*)&Amat[(size_t)gr * Kdim + k0n + ac]
                                    : make_float4(0.f, 0.f, 0.f, 0.f);
            }
            rb = *(const float4*)&Bmat[(size_t)(k0n + br) * Ndim + col0 + bc];
        }
        int cb = it & 1;
        #pragma unroll
        for (int kk = 0; kk < 16; kk += 8) {
            unsigned a[2][4], b[4][2];
            #pragma unroll
            for (int mt = 0; mt < 2; mt++) {
                int r = wm * 32 + mt * 16;
                a[mt][0] = __float_as_uint(As[cb][r + g][kk + tg]);
                a[mt][1] = __float_as_uint(As[cb][r + g + 8][kk + tg]);
                a[mt][2] = __float_as_uint(As[cb][r + g][kk + tg + 4]);
                a[mt][3] = __float_as_uint(As[cb][r + g + 8][kk + tg + 4]);
            }
            #pragma unroll
            for (int nt = 0; nt < 4; nt++) {
                int c = wn * 32 + nt * 8 + g;
                b[nt][0] = __float_as_uint(Bs[cb][kk + tg][c]);
                b[nt][1] = __float_as_uint(Bs[cb][kk + tg + 4][c]);
            }
            #pragma unroll
            for (int mt = 0; mt < 2; mt++)
                #pragma unroll
                for (int nt = 0; nt < 4; nt++) {
                    asm volatile(
                        "mma.sync.aligned.m16n8k8.row.col.f32.tf32.tf32.f32 "
                        "{%0,%1,%2,%3}, {%4,%5,%6,%7}, {%8,%9}, {%0,%1,%2,%3};\n"
                        : "+f"(acc[mt][nt][0]), "+f"(acc[mt][nt][1]),
                          "+f"(acc[mt][nt][2]), "+f"(acc[mt][nt][3])
                        : "r"(a[mt][0]), "r"(a[mt][1]), "r"(a[mt][2]), "r"(a[mt][3]),
                          "r"(b[nt][0]), "r"(b[nt][1]));
                }
        }
        if (more) {
            __syncthreads();
            int sb = (it + 1) & 1;
            #pragma unroll
            for (int i = 0; i < 2; i++) {
                int r = ar0 + i * 64;
                As[sb][r][ac + 0] = f2tf32f(ra[i].x);
                As[sb][r][ac + 1] = f2tf32f(ra[i].y);
                As[sb][r][ac + 2] = f2tf32f(ra[i].z);
                As[sb][r][ac + 3] = f2tf32f(ra[i].w);
            }
            Bs[sb][br][bc + 0] = f2tf32f(rb.x);
            Bs[sb][br][bc + 1] = f2tf32f(rb.y);
            Bs[sb][br][bc + 2] = f2tf32f(rb.z);
            Bs[sb][br][bc + 3] = f2tf32f(rb.w);
            __syncthreads();
        }
    }
    #pragma unroll
    for (int mt = 0; mt < 2; mt++) {
        int rbase = row0 + wm * 32 + mt * 16;
        #pragma unroll
        for (int nt = 0; nt < 4; nt++) {
            int c = col0 + wn * 32 + nt * 8 + tg * 2;
            int r = rbase + g;
            if (r < Mdim) *(float2*)&Cmat[(size_t)r * Ndim + c] =
                make_float2(acc[mt][nt][0], acc[mt][nt][1]);
            r = rbase + g + 8;
            if (r < Mdim) *(float2*)&Cmat[(size_t)r * Ndim + c] =
                make_float2(acc[mt][nt][2], acc[mt][nt][3]);
        }
    }
}

// ---------------------------------------------------------------------------
// Fused GAT layer 1, transpose-tile formulation.
// Block = node, warp h = head h. Per 32-edge tile: stage rows to smem,
// lane = edge for scoring, lane = channel for aggregation.
// ---------------------------------------------------------------------------
#define SSTR 36
__global__ void gat1_node_kernel(const float* __restrict__ att1,
                                 const float* __restrict__ b1) {
    __shared__ __align__(16) float stage[H1][32 * SSTR];
    __shared__ __align__(16) float sh_xr[H1][32];
    __shared__ __align__(16) float sh_at[H1][32];

    int d = blockIdx.x;
    int h = threadIdx.x >> 5, lane = threadIdx.x & 31;
    int off = h * CH1 + lane;
    float* S = stage[h];

    sh_at[h][lane] = att1[off];
    sh_xr[h][lane] = g_xr1[d * F1 + off];
    __syncwarp();

    int beg = g_rowptr[d], end = g_rowptr[d + 1];
    float m = -INFINITY, den = 0.f, acc = 0.f;

    for (int t = beg; t < end; t += 32) {
        int n = end - t; if (n > 32) n = 32;
        int idx = t + lane;
        int s = g_csrc[(idx < end) ? idx : beg];

        if (n == 32) {
            #pragma unroll 4
            for (int e = 0; e < 32; e++) {
                int se = __shfl_sync(0xFFFFFFFFu, s, e);
                S[e * SSTR + lane] = g_xl1[(size_t)se * F1 + off];
            }
        } else {
            #pragma unroll 4
            for (int e = 0; e < n; e++) {
                int se = __shfl_sync(0xFFFFFFFFu, s, e);
                S[e * SSTR + lane] = g_xl1[(size_t)se * F1 + off];
            }
        }
        __syncwarp();

        float p = -INFINITY;
        if (lane < n) {
            float dotv = 0.f;
            #pragma unroll
            for (int c = 0; c < 32; c += 4) {
                float4 xv = *(float4*)&S[lane * SSTR + c];
                float4 xr = *(float4*)&sh_xr[h][c];
                float4 at = *(float4*)&sh_at[h][c];
                dotv += at.x * leaky(xv.x + xr.x);
                dotv += at.y * leaky(xv.y + xr.y);
                dotv += at.z * leaky(xv.z + xr.z);
                dotv += at.w * leaky(xv.w + xr.w);
            }
            p = dotv;
        }

        float tmax = warpMax(p);
        float newm = fmaxf(m, tmax);
        float r = __expf(m - newm);
        den *= r; acc *= r; m = newm;
        float w = (lane < n) ? __expf(p - m) : 0.f;
        den += warpSum(w);

        if (n == 32) {
            #pragma unroll 8
            for (int e = 0; e < 32; e++) {
                float we = __shfl_sync(0xFFFFFFFFu, w, e);
                acc += we * S[e * SSTR + lane];
            }
        } else {
            for (int e = 0; e < n; e++) {
                float we = __shfl_sync(0xFFFFFFFFu, w, e);
                acc += we * S[e * SSTR + lane];
            }
        }
        __syncwarp();
    }
    float out = acc / (den + 1e-16f) + b1[off];
    g_h1[d * F1 + off] = (out > 0.f) ? out : (__expf(out) - 1.f);
}

// ---------------------------------------------------------------------------
// Fused GAT layer 2: warp per node, lane covers channels c and c+32.
// 2-edge interleaved chains.
// ---------------------------------------------------------------------------
__global__ void gat2_node_kernel(const float* __restrict__ att2, int nN) {
    int d = blockIdx.x * 4 + (threadIdx.x >> 5);
    if (d >= nN) return;
    int lane = threadIdx.x & 31;
    float a0 = att2[lane], a1 = att2[32 + lane];
    float xr0 = g_xr2[d * F2 + lane];
    float xr1 = g_xr2[d * F2 + 32 + lane];
    int beg = g_rowptr[d], end = g_rowptr[d + 1];

    float mA = -INFINITY, denA = 0.f, accA0 = 0.f, accA1 = 0.f;
    float mB = -INFINITY, denB = 0.f, accB0 = 0.f, accB1 = 0.f;

    int s0 = g_csrc[beg];
    float xa0 = g_xl2[s0 * F2 + lane];
    float xa1 = g_xl2[s0 * F2 + 32 + lane];
    float xb0 = 0.f, xb1 = 0.f;
    if (beg + 1 < end) {
        int s1 = g_csrc[beg + 1];
        xb0 = g_xl2[s1 * F2 + lane];
        xb1 = g_xl2[s1 * F2 + 32 + lane];
    }

    int j = beg;
    for (; j + 1 < end; j += 2) {
        float cA0 = xa0, cA1 = xa1, cB0 = xb0, cB1 = xb1;
        if (j + 2 < end) {
            int s = g_csrc[j + 2];
            xa0 = g_xl2[s * F2 + lane];
            xa1 = g_xl2[s * F2 + 32 + lane];
        }
        if (j + 3 < end) {
            int s = g_csrc[j + 3];
            xb0 = g_xl2[s * F2 + lane];
            xb1 = g_xl2[s * F2 + 32 + lane];
        }
        float pA = warpSum(leaky(cA0 + xr0) * a0 + leaky(cA1 + xr1) * a1);
        float pB = warpSum(leaky(cB0 + xr0) * a0 + leaky(cB1 + xr1) * a1);
        if (pA > mA) { float r = __expf(mA - pA); denA *= r; accA0 *= r; accA1 *= r; mA = pA; }
        float wA = __expf(pA - mA);
        denA += wA; accA0 += wA * cA0; accA1 += wA * cA1;
        if (pB > mB) { float r = __expf(mB - pB); denB *= r; accB0 *= r; accB1 *= r; mB = pB; }
        float wB = __expf(pB - mB);
        denB += wB; accB0 += wB * cB0; accB1 += wB * cB1;
    }
    if (j < end) {
        float pA = warpSum(leaky(xa0 + xr0) * a0 + leaky(xa1 + xr1) * a1);
        if (pA > mA) { float r = __expf(mA - pA); denA *= r; accA0 *= r; accA1 *= r; mA = pA; }
        float wA = __expf(pA - mA);
        denA += wA; accA0 += wA * xa0; accA1 += wA * xa1;
    }
    float m = fmaxf(mA, mB);
    float eA = __expf(mA - m), eB = (mB == -INFINITY) ? 0.f : __expf(mB - m);
    float den = denA * eA + denB * eB;
    float inv = 1.f / (den + 1e-16f);
    g_h2[d * F2 + lane]      = (accA0 * eA + accB0 * eB) * inv;
    g_h2[d * F2 + 32 + lane] = (accA1 * eA + accB1 * eB) * inv;
}

// ---------------------------------------------------------------------------
// InstanceNorm stats (block per channel)
// ---------------------------------------------------------------------------
__global__ void stats_kernel(int nN) {
    int c = blockIdx.x;
    __shared__ double ssum[256], ssq[256];
    double s = 0.0, q = 0.0;
    for (int i = threadIdx.x; i < nN; i += blockDim.x) {
        double v = (double)g_h2[i * F2 + c];
        s += v; q += v * v;
    }
    ssum[threadIdx.x] = s; ssq[threadIdx.x] = q;
    __syncthreads();
    for (int o = 128; o > 0; o >>= 1) {
        if (threadIdx.x < o) {
            ssum[threadIdx.x] += ssum[threadIdx.x + o];
            ssq[threadIdx.x]  += ssq[threadIdx.x + o];
        }
        __syncthreads();
    }
    if (threadIdx.x == 0) {
        double mean = ssum[0] / nN;
        double var  = ssq[0] / nN - mean * mean;
        g_mean[c] = (float)mean;
        g_rstd[c] = (float)(1.0 / sqrt(var + 1e-5));
    }
}

// ---------------------------------------------------------------------------
// Normalize + log_softmax
// ---------------------------------------------------------------------------
__global__ void finalize_kernel(const float* __restrict__ gamma,
                                const float* __restrict__ beta,
                                float* __restrict__ out, int nN) {
    int node = blockIdx.x * 4 + (threadIdx.x >> 5);
    if (node >= nN) return;
    int lane = threadIdx.x & 31;
    int c0 = lane, c1 = lane + 32;
    float y0 = (g_h2[node * F2 + c0] - g_mean[c0]) * g_rstd[c0] * gamma[c0] + beta[c0];
    float y1 = (g_h2[node * F2 + c1] - g_mean[c1]) * g_rstd[c1] * gamma[c1] + beta[c1];
    out[node * F2 + c0] = y0;
    out[node * F2 + c1] = y1;
    float m = warpMax(fmaxf(y0, y1));
    float ssum = warpSum(expf(y0 - m) + expf(y1 - m));
    float lse = m + logf(ssum);
    float* out2 = out + (size_t)nN * F2;
    out2[node * F2 + c0] = y0 - lse;
    out2[node * F2 + c1] = y1 - lse;
}

// ---------------------------------------------------------------------------
// Launcher
// ---------------------------------------------------------------------------
extern "C" void kernel_launch(void* const* d_in, const int* in_sizes, int n_in,
                              void* d_out, int out_size) {
    const float* x     = (const float*)d_in[0];
    const float* Wl1   = (const float*)d_in[1];
    const float* Wr1   = (const float*)d_in[2];
    const float* att1  = (const float*)d_in[3];
    const float* b1    = (const float*)d_in[4];
    const float* Wl2   = (const float*)d_in[5];
    const float* Wr2   = (const float*)d_in[6];
    const float* att2  = (const float*)d_in[7];
    const float* gamma = (const float*)d_in[9];
    const float* beta  = (const float*)d_in[10];
    const int*   ei    = (const int*)d_in[11];

    int nN = in_sizes[0] / F0;
    int nE = in_sizes[11] / 2;
    int nET = nE + nN;
    const int* src = ei;
    const int* dst = ei + nE;

    float *xl1, *xr1, *h1, *xl2, *xr2;
    cudaGetSymbolAddress((void**)&xl1, g_xl1);
    cudaGetSymbolAddress((void**)&xr1, g_xr1);
    cudaGetSymbolAddress((void**)&h1,  g_h1);
    cudaGetSymbolAddress((void**)&xl2, g_xl2);
    cudaGetSymbolAddress((void**)&xr2, g_xr2);

    // CSR build
    zero_deg_kernel<<<(nN + 255) / 256, 256>>>(nN);
    hist_kernel<<<(nET + 255) / 256, 256>>>(dst, nE, nET);
    scan_kernel<<<1, 1024>>>(nN);
    scatter_kernel<<<(nET + 255) / 256, 256>>>(src, dst, nE, nET);

    // Layer 1: both GEMMs in one launch (z selects Wl/Wr)
    {
        dim3 grid(F1 / 64, (nN + 127) / 128, 2);
        mma_gemm2_kernel<<<grid, 256>>>(x, Wl1, Wr1, xl1, xr1, nN, F0, F1);
    }
    gat1_node_kernel<<<nN, 256>>>(att1, b1);

    // Layer 2: both GEMMs in one launch
    {
        dim3 grid(F2 / 64, (nN + 127) / 128, 2);
        mma_gemm2_kernel<<<grid, 256>>>(h1, Wl2, Wr2, xl2, xr2, nN, F1, F2);
    }
    gat2_node_kernel<<<(nN + 3) / 4, 128>>>(att2, nN);

    // InstanceNorm + log_softmax
    stats_kernel<<<F2, 256>>>(nN);
    finalize_kernel<<<(nN + 3) / 4, 128>>>(gamma, beta, (float*)d_out, nN);
}

// round 6
// speedup vs baseline: 4.4019x; 1.0435x over previous
#include <cuda_runtime.h>
#include <math.h>

#define MAXN 20000
#define MAXE 320000
#define MAXET (MAXE + MAXN)
#define H1 8
#define CH1 32
#define F1 256
#define F0 128
#define F2 64

// ---------------------------------------------------------------------------
// Scratch
// ---------------------------------------------------------------------------
__device__ float g_xl1[MAXN * F1];
__device__ float g_xr1[MAXN * F1];
__device__ float g_h1 [MAXN * F1];
__device__ float g_xl2[MAXN * F2];
__device__ float g_xr2[MAXN * F2];
__device__ float g_h2 [MAXN * F2];

__device__ int g_deg[MAXN];
__device__ int g_rowptr[MAXN + 1];
__device__ int g_cursor[MAXN];
__device__ int g_csrc[MAXET];

__device__ float g_fsum[F2];
__device__ float g_fsq [F2];

// ---------------------------------------------------------------------------
// Helpers
// ---------------------------------------------------------------------------
__device__ __forceinline__ float warpSum(float v) {
    #pragma unroll
    for (int o = 16; o > 0; o >>= 1) v += __shfl_xor_sync(0xFFFFFFFFu, v, o);
    return v;
}
__device__ __forceinline__ float warpMax(float v) {
    #pragma unroll
    for (int o = 16; o > 0; o >>= 1) v = fmaxf(v, __shfl_xor_sync(0xFFFFFFFFu, v, o));
    return v;
}
__device__ __forceinline__ float f2tf32f(float x) {
    unsigned u;
    asm("cvt.rna.tf32.f32 %0, %1;" : "=r"(u) : "f"(x));
    return __uint_as_float(u);
}
__device__ __forceinline__ float leaky(float v) { return fmaxf(v, 0.2f * v); }

// ---------------------------------------------------------------------------
// CSR build (runs on side stream, overlapped with layer-1 GEMM)
// ---------------------------------------------------------------------------
__global__ void zero_deg_kernel(int nN) {
    int i = blockIdx.x * blockDim.x + threadIdx.x;
    if (i < nN) g_deg[i] = 0;
    if (i < F2) { g_fsum[i] = 0.f; g_fsq[i] = 0.f; }
}

__global__ void hist_kernel(const int* __restrict__ dst, int nE, int nET) {
    int i = blockIdx.x * blockDim.x + threadIdx.x;
    if (i >= nET) return;
    int d = (i < nE) ? dst[i] : i - nE;
    atomicAdd(&g_deg[d], 1);
}

#define SCAN_CHUNK 20
__global__ void scan_kernel(int nN) {
    __shared__ int sh[1024];
    int tid = threadIdx.x;
    int start = tid * SCAN_CHUNK;
    int cnt = nN - start;
    if (cnt < 0) cnt = 0;
    if (cnt > SCAN_CHUNK) cnt = SCAN_CHUNK;
    int vals[SCAN_CHUNK];
    int sum = 0;
    for (int i = 0; i < cnt; i++) { vals[i] = g_deg[start + i]; sum += vals[i]; }
    sh[tid] = sum;
    __syncthreads();
    #pragma unroll
    for (int o = 1; o < 1024; o <<= 1) {
        int t = (tid >= o) ? sh[tid - o] : 0;
        __syncthreads();
        sh[tid] += t;
        __syncthreads();
    }
    int run = sh[tid] - sum;
    for (int i = 0; i < cnt; i++) {
        g_rowptr[start + i] = run;
        g_cursor[start + i] = run;
        run += vals[i];
    }
    if (tid == 1023) g_rowptr[nN] = sh[1023];
}

__global__ void scatter_kernel(const int* __restrict__ src,
                               const int* __restrict__ dst, int nE, int nET) {
    int i = blockIdx.x * blockDim.x + threadIdx.x;
    if (i >= nET) return;
    int s, d;
    if (i < nE) { s = src[i]; d = dst[i]; } else { s = d = i - nE; }
    int slot = atomicAdd(&g_cursor[d], 1);
    g_csrc[slot] = s;
}

// ---------------------------------------------------------------------------
// Pipelined TF32 GEMM: BM=128, BN=64, BK=16, 256 threads (8 warps, 4x2).
// blockIdx.z selects (Bl,outL) or (Br,outR).
// ---------------------------------------------------------------------------
#define PADA 20
#define PADB 72
__global__ void __launch_bounds__(256, 2)
mma_gemm2_kernel(const float* __restrict__ Amat,
                 const float* __restrict__ Bl,
                 const float* __restrict__ Br,
                 float* __restrict__ outL,
                 float* __restrict__ outR,
                 int Mdim, int Kdim, int Ndim) {
    const float* Bmat = blockIdx.z ? Br : Bl;
    float*       Cmat = blockIdx.z ? outR : outL;
    __shared__ __align__(16) float As[2][128][PADA];
    __shared__ __align__(16) float Bs[2][16][PADB];
    int tid = threadIdx.x;
    int lane = tid & 31, warp = tid >> 5;
    int wm = warp >> 1, wn = warp & 1;
    int g = lane >> 2, tg = lane & 3;
    int row0 = blockIdx.y * 128, col0 = blockIdx.x * 64;

    int ar0 = tid >> 2, ac = (tid & 3) * 4;
    int br = tid >> 4, bc = (tid & 15) * 4;

    float4 ra[2], rb;

    float acc[2][4][4];
    #pragma unroll
    for (int i = 0; i < 2; i++)
        #pragma unroll
        for (int j = 0; j < 4; j++)
            #pragma unroll
            for (int k = 0; k < 4; k++) acc[i][j][k] = 0.f;

    int nit = Kdim / 16;

    #pragma unroll
    for (int i = 0; i < 2; i++) {
        int gr = row0 + ar0 + i * 64;
        ra[i] = (gr < Mdim) ? *(const float4*)&Amat[(size_t)gr * Kdim + ac]
                            : make_float4(0.f, 0.f, 0.f, 0.f);
    }
    rb = *(const float4*)&Bmat[(size_t)br * Ndim + col0 + bc];
    #pragma unroll
    for (int i = 0; i < 2; i++) {
        int r = ar0 + i * 64;
        As[0][r][ac + 0] = f2tf32f(ra[i].x);
        As[0][r][ac + 1] = f2tf32f(ra[i].y);
        As[0][r][ac + 2] = f2tf32f(ra[i].z);
        As[0][r][ac + 3] = f2tf32f(ra[i].w);
    }
    Bs[0][br][bc + 0] = f2tf32f(rb.x);
    Bs[0][br][bc + 1] = f2tf32f(rb.y);
    Bs[0][br][bc + 2] = f2tf32f(rb.z);
    Bs[0][br][bc + 3] = f2tf32f(rb.w);
    __syncthreads();

    for (int it = 0; it < nit; it++) {
        int k0n = (it + 1) * 16;
        bool more = (it + 1) < nit;
        if (more) {
            #pragma unroll
            for (int i = 0; i < 2; i++) {
                int gr = row0 + ar0 + i * 64;
                ra[i] = (gr < Mdim) ? *(const float4*)&Amat[(size_t)gr * Kdim + k0n + ac]
                                    : make_float4(0.f, 0.f, 0.f, 0.f);
            }
            rb = *(const float4*)&Bmat[(size_t)(k0n + br) * Ndim + col0 + bc];
        }
        int cb = it & 1;
        #pragma unroll
        for (int kk = 0; kk < 16; kk += 8) {
            unsigned a[2][4], b[4][2];
            #pragma unroll
            for (int mt = 0; mt < 2; mt++) {
                int r = wm * 32 + mt * 16;
                a[mt][0] = __float_as_uint(As[cb][r + g][kk + tg]);
                a[mt][1] = __float_as_uint(As[cb][r + g + 8][kk + tg]);
                a[mt][2] = __float_as_uint(As[cb][r + g][kk + tg + 4]);
                a[mt][3] = __float_as_uint(As[cb][r + g + 8][kk + tg + 4]);
            }
            #pragma unroll
            for (int nt = 0; nt < 4; nt++) {
                int c = wn * 32 + nt * 8 + g;
                b[nt][0] = __float_as_uint(Bs[cb][kk + tg][c]);
                b[nt][1] = __float_as_uint(Bs[cb][kk + tg + 4][c]);
            }
            #pragma unroll
            for (int mt = 0; mt < 2; mt++)
                #pragma unroll
                for (int nt = 0; nt < 4; nt++) {
                    asm volatile(
                        "mma.sync.aligned.m16n8k8.row.col.f32.tf32.tf32.f32 "
                        "{%0,%1,%2,%3}, {%4,%5,%6,%7}, {%8,%9}, {%0,%1,%2,%3};\n"
                        : "+f"(acc[mt][nt][0]), "+f"(acc[mt][nt][1]),
                          "+f"(acc[mt][nt][2]), "+f"(acc[mt][nt][3])
                        : "r"(a[mt][0]), "r"(a[mt][1]), "r"(a[mt][2]), "r"(a[mt][3]),
                          "r"(b[nt][0]), "r"(b[nt][1]));
                }
        }
        if (more) {
            __syncthreads();
            int sb = (it + 1) & 1;
            #pragma unroll
            for (int i = 0; i < 2; i++) {
                int r = ar0 + i * 64;
                As[sb][r][ac + 0] = f2tf32f(ra[i].x);
                As[sb][r][ac + 1] = f2tf32f(ra[i].y);
                As[sb][r][ac + 2] = f2tf32f(ra[i].z);
                As[sb][r][ac + 3] = f2tf32f(ra[i].w);
            }
            Bs[sb][br][bc + 0] = f2tf32f(rb.x);
            Bs[sb][br][bc + 1] = f2tf32f(rb.y);
            Bs[sb][br][bc + 2] = f2tf32f(rb.z);
            Bs[sb][br][bc + 3] = f2tf32f(rb.w);
            __syncthreads();
        }
    }
    #pragma unroll
    for (int mt = 0; mt < 2; mt++) {
        int rbase = row0 + wm * 32 + mt * 16;
        #pragma unroll
        for (int nt = 0; nt < 4; nt++) {
            int c = col0 + wn * 32 + nt * 8 + tg * 2;
            int r = rbase + g;
            if (r < Mdim) *(float2*)&Cmat[(size_t)r * Ndim + c] =
                make_float2(acc[mt][nt][0], acc[mt][nt][1]);
            r = rbase + g + 8;
            if (r < Mdim) *(float2*)&Cmat[(size_t)r * Ndim + c] =
                make_float2(acc[mt][nt][2], acc[mt][nt][3]);
        }
    }
}

// ---------------------------------------------------------------------------
// Fused GAT layer 1, transpose-tile with shared index array + float4 staging.
// Block = node, warp h = head h.
// ---------------------------------------------------------------------------
#define SSTR 36
__global__ void gat1_node_kernel(const float* __restrict__ att1,
                                 const float* __restrict__ b1) {
    __shared__ __align__(16) float stage[H1][32 * SSTR];
    __shared__ __align__(16) float sh_xr[H1][32];
    __shared__ __align__(16) float sh_at[H1][32];
    __shared__ int sIdx[32];

    int d = blockIdx.x;
    int h = threadIdx.x >> 5, lane = threadIdx.x & 31;
    int off = h * CH1 + lane;
    float* S = stage[h];

    sh_at[h][lane] = att1[off];
    sh_xr[h][lane] = g_xr1[d * F1 + off];

    int beg = g_rowptr[d], end = g_rowptr[d + 1];
    float m = -INFINITY, den = 0.f, acc = 0.f;

    // staging geometry: 8 lanes per edge-row (float4 each), 4 rows per pass
    int erow = lane >> 3;          // 0..3
    int c4   = (lane & 7) * 4;     // 0..28

    for (int t = beg; t < end; t += 32) {
        int n = end - t; if (n > 32) n = 32;
        if (h == 0) {
            int idx = t + lane;
            sIdx[lane] = g_csrc[(idx < end) ? idx : beg];
        }
        __syncthreads();

        // stage 32 edge rows x 32 channels (this head) via float4
        #pragma unroll
        for (int p = 0; p < 8; p++) {
            int e = p * 4 + erow;
            int se = sIdx[e];
            float4 v = *(const float4*)&g_xl1[(size_t)se * F1 + h * CH1 + c4];
            *(float4*)&S[e * SSTR + c4] = v;
        }
        __syncwarp();

        // score for edge 'lane'
        float p = -INFINITY;
        if (lane < n) {
            float d0 = 0.f, d1 = 0.f;
            #pragma unroll
            for (int c = 0; c < 32; c += 8) {
                float4 xv0 = *(float4*)&S[lane * SSTR + c];
                float4 xr0 = *(float4*)&sh_xr[h][c];
                float4 at0 = *(float4*)&sh_at[h][c];
                float4 xv1 = *(float4*)&S[lane * SSTR + c + 4];
                float4 xr1 = *(float4*)&sh_xr[h][c + 4];
                float4 at1 = *(float4*)&sh_at[h][c + 4];
                d0 += at0.x * leaky(xv0.x + xr0.x);
                d0 += at0.y * leaky(xv0.y + xr0.y);
                d0 += at0.z * leaky(xv0.z + xr0.z);
                d0 += at0.w * leaky(xv0.w + xr0.w);
                d1 += at1.x * leaky(xv1.x + xr1.x);
                d1 += at1.y * leaky(xv1.y + xr1.y);
                d1 += at1.z * leaky(xv1.z + xr1.z);
                d1 += at1.w * leaky(xv1.w + xr1.w);
            }
            p = d0 + d1;
        }

        // tile softmax combine
        float tmax = warpMax(p);
        float newm = fmaxf(m, tmax);
        float r = __expf(m - newm);
        den *= r; acc *= r; m = newm;
        float w = (lane < n) ? __expf(p - m) : 0.f;
        den += warpSum(w);

        // aggregate: acc(channel=lane) += sum_e w_e * S[e][lane]
        if (n == 32) {
            #pragma unroll 8
            for (int e = 0; e < 32; e++) {
                float we = __shfl_sync(0xFFFFFFFFu, w, e);
                acc += we * S[e * SSTR + lane];
            }
        } else {
            for (int e = 0; e < n; e++) {
                float we = __shfl_sync(0xFFFFFFFFu, w, e);
                acc += we * S[e * SSTR + lane];
            }
        }
        __syncthreads();
    }
    float out = acc / (den + 1e-16f) + b1[off];
    g_h1[d * F1 + off] = (out > 0.f) ? out : (__expf(out) - 1.f);
}

// ---------------------------------------------------------------------------
// Fused GAT layer 2: warp per node, lane covers channels c and c+32.
// ---------------------------------------------------------------------------
__global__ void gat2_node_kernel(const float* __restrict__ att2, int nN) {
    int d = blockIdx.x * 4 + (threadIdx.x >> 5);
    if (d >= nN) return;
    int lane = threadIdx.x & 31;
    float a0 = att2[lane], a1 = att2[32 + lane];
    float xr0 = g_xr2[d * F2 + lane];
    float xr1 = g_xr2[d * F2 + 32 + lane];
    int beg = g_rowptr[d], end = g_rowptr[d + 1];

    float mA = -INFINITY, denA = 0.f, accA0 = 0.f, accA1 = 0.f;
    float mB = -INFINITY, denB = 0.f, accB0 = 0.f, accB1 = 0.f;

    int s0 = g_csrc[beg];
    float xa0 = g_xl2[s0 * F2 + lane];
    float xa1 = g_xl2[s0 * F2 + 32 + lane];
    float xb0 = 0.f, xb1 = 0.f;
    if (beg + 1 < end) {
        int s1 = g_csrc[beg + 1];
        xb0 = g_xl2[s1 * F2 + lane];
        xb1 = g_xl2[s1 * F2 + 32 + lane];
    }

    int j = beg;
    for (; j + 1 < end; j += 2) {
        float cA0 = xa0, cA1 = xa1, cB0 = xb0, cB1 = xb1;
        if (j + 2 < end) {
            int s = g_csrc[j + 2];
            xa0 = g_xl2[s * F2 + lane];
            xa1 = g_xl2[s * F2 + 32 + lane];
        }
        if (j + 3 < end) {
            int s = g_csrc[j + 3];
            xb0 = g_xl2[s * F2 + lane];
            xb1 = g_xl2[s * F2 + 32 + lane];
        }
        float pA = warpSum(leaky(cA0 + xr0) * a0 + leaky(cA1 + xr1) * a1);
        float pB = warpSum(leaky(cB0 + xr0) * a0 + leaky(cB1 + xr1) * a1);
        if (pA > mA) { float r = __expf(mA - pA); denA *= r; accA0 *= r; accA1 *= r; mA = pA; }
        float wA = __expf(pA - mA);
        denA += wA; accA0 += wA * cA0; accA1 += wA * cA1;
        if (pB > mB) { float r = __expf(mB - pB); denB *= r; accB0 *= r; accB1 *= r; mB = pB; }
        float wB = __expf(pB - mB);
        denB += wB; accB0 += wB * cB0; accB1 += wB * cB1;
    }
    if (j < end) {
        float pA = warpSum(leaky(xa0 + xr0) * a0 + leaky(xa1 + xr1) * a1);
        if (pA > mA) { float r = __expf(mA - pA); denA *= r; accA0 *= r; accA1 *= r; mA = pA; }
        float wA = __expf(pA - mA);
        denA += wA; accA0 += wA * xa0; accA1 += wA * xa1;
    }
    float m = fmaxf(mA, mB);
    float eA = __expf(mA - m), eB = (mB == -INFINITY) ? 0.f : __expf(mB - m);
    float den = denA * eA + denB * eB;
    float inv = 1.f / (den + 1e-16f);
    g_h2[d * F2 + lane]      = (accA0 * eA + accB0 * eB) * inv;
    g_h2[d * F2 + 32 + lane] = (accA1 * eA + accB1 * eB) * inv;
}

// ---------------------------------------------------------------------------
// InstanceNorm stats: coalesced, warp-per-row-stripe, float atomics
// ---------------------------------------------------------------------------
__global__ void stats_kernel(int nN) {
    int gw = (blockIdx.x * blockDim.x + threadIdx.x) >> 5;
    int nw = (gridDim.x * blockDim.x) >> 5;
    int lane = threadIdx.x & 31;
    float s0 = 0.f, q0 = 0.f, s1 = 0.f, q1 = 0.f;
    for (int i = gw; i < nN; i += nw) {
        float v0 = g_h2[i * F2 + lane];
        float v1 = g_h2[i * F2 + 32 + lane];
        s0 += v0; q0 += v0 * v0;
        s1 += v1; q1 += v1 * v1;
    }
    atomicAdd(&g_fsum[lane], s0);
    atomicAdd(&g_fsq [lane], q0);
    atomicAdd(&g_fsum[32 + lane], s1);
    atomicAdd(&g_fsq [32 + lane], q1);
}

// ---------------------------------------------------------------------------
// Normalize + log_softmax (mean/rstd computed inline)
// ---------------------------------------------------------------------------
__global__ void finalize_kernel(const float* __restrict__ gamma,
                                const float* __restrict__ beta,
                                float* __restrict__ out, int nN) {
    int node = blockIdx.x * 4 + (threadIdx.x >> 5);
    if (node >= nN) return;
    int lane = threadIdx.x & 31;
    int c0 = lane, c1 = lane + 32;
    float invN = 1.f / (float)nN;
    float mean0 = g_fsum[c0] * invN;
    float mean1 = g_fsum[c1] * invN;
    float var0 = g_fsq[c0] * invN - mean0 * mean0;
    float var1 = g_fsq[c1] * invN - mean1 * mean1;
    float rstd0 = rsqrtf(var0 + 1e-5f);
    float rstd1 = rsqrtf(var1 + 1e-5f);
    float y0 = (g_h2[node * F2 + c0] - mean0) * rstd0 * gamma[c0] + beta[c0];
    float y1 = (g_h2[node * F2 + c1] - mean1) * rstd1 * gamma[c1] + beta[c1];
    out[node * F2 + c0] = y0;
    out[node * F2 + c1] = y1;
    float m = warpMax(fmaxf(y0, y1));
    float ssum = warpSum(expf(y0 - m) + expf(y1 - m));
    float lse = m + logf(ssum);
    float* out2 = out + (size_t)nN * F2;
    out2[node * F2 + c0] = y0 - lse;
    out2[node * F2 + c1] = y1 - lse;
}

// ---------------------------------------------------------------------------
// Launcher — CSR build forked onto side stream, overlapped with layer-1 GEMM
// ---------------------------------------------------------------------------
static cudaStream_t s_side = nullptr;
static cudaEvent_t  s_ev0 = nullptr, s_ev1 = nullptr;

extern "C" void kernel_launch(void* const* d_in, const int* in_sizes, int n_in,
                              void* d_out, int out_size) {
    const float* x     = (const float*)d_in[0];
    const float* Wl1   = (const float*)d_in[1];
    const float* Wr1   = (const float*)d_in[2];
    const float* att1  = (const float*)d_in[3];
    const float* b1    = (const float*)d_in[4];
    const float* Wl2   = (const float*)d_in[5];
    const float* Wr2   = (const float*)d_in[6];
    const float* att2  = (const float*)d_in[7];
    const float* gamma = (const float*)d_in[9];
    const float* beta  = (const float*)d_in[10];
    const int*   ei    = (const int*)d_in[11];

    int nN = in_sizes[0] / F0;
    int nE = in_sizes[11] / 2;
    int nET = nE + nN;
    const int* src = ei;
    const int* dst = ei + nE;

    if (s_side == nullptr) {
        cudaStreamCreateWithFlags(&s_side, cudaStreamNonBlocking);
        cudaEventCreateWithFlags(&s_ev0, cudaEventDisableTiming);
        cudaEventCreateWithFlags(&s_ev1, cudaEventDisableTiming);
    }

    float *xl1, *xr1, *h1, *xl2, *xr2;
    cudaGetSymbolAddress((void**)&xl1, g_xl1);
    cudaGetSymbolAddress((void**)&xr1, g_xr1);
    cudaGetSymbolAddress((void**)&h1,  g_h1);
    cudaGetSymbolAddress((void**)&xl2, g_xl2);
    cudaGetSymbolAddress((void**)&xr2, g_xr2);

    // Fork: CSR build on side stream
    cudaEventRecord(s_ev0, 0);
    cudaStreamWaitEvent(s_side, s_ev0, 0);
    zero_deg_kernel<<<(nN + 255) / 256, 256, 0, s_side>>>(nN);
    hist_kernel<<<(nET + 255) / 256, 256, 0, s_side>>>(dst, nE, nET);
    scan_kernel<<<1, 1024, 0, s_side>>>(nN);
    scatter_kernel<<<(nET + 255) / 256, 256, 0, s_side>>>(src, dst, nE, nET);
    cudaEventRecord(s_ev1, s_side);

    // Main: layer-1 GEMMs concurrent with CSR
    {
        dim3 grid(F1 / 64, (nN + 127) / 128, 2);
        mma_gemm2_kernel<<<grid, 256>>>(x, Wl1, Wr1, xl1, xr1, nN, F0, F1);
    }
    // Join
    cudaStreamWaitEvent(0, s_ev1, 0);

    gat1_node_kernel<<<nN, 256>>>(att1, b1);

    {
        dim3 grid(F2 / 64, (nN + 127) / 128, 2);
        mma_gemm2_kernel<<<grid, 256>>>(h1, Wl2, Wr2, xl2, xr2, nN, F1, F2);
    }
    gat2_node_kernel<<<(nN + 3) / 4, 128>>>(att2, nN);

    stats_kernel<<<64, 256>>>(nN);
    finalize_kernel<<<(nN + 3) / 4, 128>>>(gamma, beta, (float*)d_out, nN);
}

// round 7
// speedup vs baseline: 4.7133x; 1.0708x over previous
#include <cuda_runtime.h>
#include <math.h>

#define MAXN 20000
#define MAXE 320000
#define MAXET (MAXE + MAXN)
#define H1 8
#define CH1 32
#define F1 256
#define F0 128
#define F2 64

// ---------------------------------------------------------------------------
// Scratch
// ---------------------------------------------------------------------------
__device__ float g_xl1[MAXN * F1];
__device__ float g_xr1[MAXN * F1];
__device__ float g_h1 [MAXN * F1];
__device__ float g_xl2[MAXN * F2];
__device__ float g_xr2[MAXN * F2];
__device__ float g_h2 [MAXN * F2];

__device__ int g_deg[MAXN];
__device__ int g_rowptr[MAXN + 1];
__device__ int g_cursor[MAXN];
__device__ int g_csrc[MAXET];

__device__ float g_fsum[F2];
__device__ float g_fsq [F2];

// ---------------------------------------------------------------------------
// Helpers
// ---------------------------------------------------------------------------
__device__ __forceinline__ float warpSum(float v) {
    #pragma unroll
    for (int o = 16; o > 0; o >>= 1) v += __shfl_xor_sync(0xFFFFFFFFu, v, o);
    return v;
}
__device__ __forceinline__ float warpMax(float v) {
    #pragma unroll
    for (int o = 16; o > 0; o >>= 1) v = fmaxf(v, __shfl_xor_sync(0xFFFFFFFFu, v, o));
    return v;
}
__device__ __forceinline__ float f2tf32f(float x) {
    unsigned u;
    asm("cvt.rna.tf32.f32 %0, %1;" : "=r"(u) : "f"(x));
    return __uint_as_float(u);
}
__device__ __forceinline__ float leaky(float v) { return fmaxf(v, 0.2f * v); }

// ---------------------------------------------------------------------------
// CSR build (runs on side stream, overlapped with layer-1 GEMM)
// ---------------------------------------------------------------------------
__global__ void zero_deg_kernel(int nN) {
    int i = blockIdx.x * blockDim.x + threadIdx.x;
    if (i < nN) g_deg[i] = 0;
    if (i < F2) { g_fsum[i] = 0.f; g_fsq[i] = 0.f; }
}

__global__ void hist_kernel(const int* __restrict__ dst, int nE, int nET) {
    int i = blockIdx.x * blockDim.x + threadIdx.x;
    if (i >= nET) return;
    int d = (i < nE) ? dst[i] : i - nE;
    atomicAdd(&g_deg[d], 1);
}

#define SCAN_CHUNK 20
__global__ void scan_kernel(int nN) {
    __shared__ int sh[1024];
    int tid = threadIdx.x;
    int start = tid * SCAN_CHUNK;
    int cnt = nN - start;
    if (cnt < 0) cnt = 0;
    if (cnt > SCAN_CHUNK) cnt = SCAN_CHUNK;
    int vals[SCAN_CHUNK];
    int sum = 0;
    for (int i = 0; i < cnt; i++) { vals[i] = g_deg[start + i]; sum += vals[i]; }
    sh[tid] = sum;
    __syncthreads();
    #pragma unroll
    for (int o = 1; o < 1024; o <<= 1) {
        int t = (tid >= o) ? sh[tid - o] : 0;
        __syncthreads();
        sh[tid] += t;
        __syncthreads();
    }
    int run = sh[tid] - sum;
    for (int i = 0; i < cnt; i++) {
        g_rowptr[start + i] = run;
        g_cursor[start + i] = run;
        run += vals[i];
    }
    if (tid == 1023) g_rowptr[nN] = sh[1023];
}

__global__ void scatter_kernel(const int* __restrict__ src,
                               const int* __restrict__ dst, int nE, int nET) {
    int i = blockIdx.x * blockDim.x + threadIdx.x;
    if (i >= nET) return;
    int s, d;
    if (i < nE) { s = src[i]; d = dst[i]; } else { s = d = i - nE; }
    int slot = atomicAdd(&g_cursor[d], 1);
    g_csrc[slot] = s;
}

// ---------------------------------------------------------------------------
// Pipelined TF32 GEMM: BM=128, BN=64, BK=16, 256 threads (8 warps, 4x2).
// ---------------------------------------------------------------------------
#define PADA 20
#define PADB 72
__global__ void __launch_bounds__(256, 2)
mma_gemm2_kernel(const float* __restrict__ Amat,
                 const float* __restrict__ Bl,
                 const float* __restrict__ Br,
                 float* __restrict__ outL,
                 float* __restrict__ outR,
                 int Mdim, int Kdim, int Ndim) {
    const float* Bmat = blockIdx.z ? Br : Bl;
    float*       Cmat = blockIdx.z ? outR : outL;
    __shared__ __align__(16) float As[2][128][PADA];
    __shared__ __align__(16) float Bs[2][16][PADB];
    int tid = threadIdx.x;
    int lane = tid & 31, warp = tid >> 5;
    int wm = warp >> 1, wn = warp & 1;
    int g = lane >> 2, tg = lane & 3;
    int row0 = blockIdx.y * 128, col0 = blockIdx.x * 64;

    int ar0 = tid >> 2, ac = (tid & 3) * 4;
    int br = tid >> 4, bc = (tid & 15) * 4;

    float4 ra[2], rb;

    float acc[2][4][4];
    #pragma unroll
    for (int i = 0; i < 2; i++)
        #pragma unroll
        for (int j = 0; j < 4; j++)
            #pragma unroll
            for (int k = 0; k < 4; k++) acc[i][j][k] = 0.f;

    int nit = Kdim / 16;

    #pragma unroll
    for (int i = 0; i < 2; i++) {
        int gr = row0 + ar0 + i * 64;
        ra[i] = (gr < Mdim) ? *(const float4*)&Amat[(size_t)gr * Kdim + ac]
                            : make_float4(0.f, 0.f, 0.f, 0.f);
    }
    rb = *(const float4*)&Bmat[(size_t)br * Ndim + col0 + bc];
    #pragma unroll
    for (int i = 0; i < 2; i++) {
        int r = ar0 + i * 64;
        As[0][r][ac + 0] = f2tf32f(ra[i].x);
        As[0][r][ac + 1] = f2tf32f(ra[i].y);
        As[0][r][ac + 2] = f2tf32f(ra[i].z);
        As[0][r][ac + 3] = f2tf32f(ra[i].w);
    }
    Bs[0][br][bc + 0] = f2tf32f(rb.x);
    Bs[0][br][bc + 1] = f2tf32f(rb.y);
    Bs[0][br][bc + 2] = f2tf32f(rb.z);
    Bs[0][br][bc + 3] = f2tf32f(rb.w);
    __syncthreads();

    for (int it = 0; it < nit; it++) {
        int k0n = (it + 1) * 16;
        bool more = (it + 1) < nit;
        if (more) {
            #pragma unroll
            for (int i = 0; i < 2; i++) {
                int gr = row0 + ar0 + i * 64;
                ra[i] = (gr < Mdim) ? *(const float4*)&Amat[(size_t)gr * Kdim + k0n + ac]
                                    : make_float4(0.f, 0.f, 0.f, 0.f);
            }
            rb = *(const float4*)&Bmat[(size_t)(k0n + br) * Ndim + col0 + bc];
        }
        int cb = it & 1;
        #pragma unroll
        for (int kk = 0; kk < 16; kk += 8) {
            unsigned a[2][4], b[4][2];
            #pragma unroll
            for (int mt = 0; mt < 2; mt++) {
                int r = wm * 32 + mt * 16;
                a[mt][0] = __float_as_uint(As[cb][r + g][kk + tg]);
                a[mt][1] = __float_as_uint(As[cb][r + g + 8][kk + tg]);
                a[mt][2] = __float_as_uint(As[cb][r + g][kk + tg + 4]);
                a[mt][3] = __float_as_uint(As[cb][r + g + 8][kk + tg + 4]);
            }
            #pragma unroll
            for (int nt = 0; nt < 4; nt++) {
                int c = wn * 32 + nt * 8 + g;
                b[nt][0] = __float_as_uint(Bs[cb][kk + tg][c]);
                b[nt][1] = __float_as_uint(Bs[cb][kk + tg + 4][c]);
            }
            #pragma unroll
            for (int mt = 0; mt < 2; mt++)
                #pragma unroll
                for (int nt = 0; nt < 4; nt++) {
                    asm volatile(
                        "mma.sync.aligned.m16n8k8.row.col.f32.tf32.tf32.f32 "
                        "{%0,%1,%2,%3}, {%4,%5,%6,%7}, {%8,%9}, {%0,%1,%2,%3};\n"
                        : "+f"(acc[mt][nt][0]), "+f"(acc[mt][nt][1]),
                          "+f"(acc[mt][nt][2]), "+f"(acc[mt][nt][3])
                        : "r"(a[mt][0]), "r"(a[mt][1]), "r"(a[mt][2]), "r"(a[mt][3]),
                          "r"(b[nt][0]), "r"(b[nt][1]));
                }
        }
        if (more) {
            __syncthreads();
            int sb = (it + 1) & 1;
            #pragma unroll
            for (int i = 0; i < 2; i++) {
                int r = ar0 + i * 64;
                As[sb][r][ac + 0] = f2tf32f(ra[i].x);
                As[sb][r][ac + 1] = f2tf32f(ra[i].y);
                As[sb][r][ac + 2] = f2tf32f(ra[i].z);
                As[sb][r][ac + 3] = f2tf32f(ra[i].w);
            }
            Bs[sb][br][bc + 0] = f2tf32f(rb.x);
            Bs[sb][br][bc + 1] = f2tf32f(rb.y);
            Bs[sb][br][bc + 2] = f2tf32f(rb.z);
            Bs[sb][br][bc + 3] = f2tf32f(rb.w);
            __syncthreads();
        }
    }
    #pragma unroll
    for (int mt = 0; mt < 2; mt++) {
        int rbase = row0 + wm * 32 + mt * 16;
        #pragma unroll
        for (int nt = 0; nt < 4; nt++) {
            int c = col0 + wn * 32 + nt * 8 + tg * 2;
            int r = rbase + g;
            if (r < Mdim) *(float2*)&Cmat[(size_t)r * Ndim + c] =
                make_float2(acc[mt][nt][0], acc[mt][nt][1]);
            r = rbase + g + 8;
            if (r < Mdim) *(float2*)&Cmat[(size_t)r * Ndim + c] =
                make_float2(acc[mt][nt][2], acc[mt][nt][3]);
        }
    }
}

// ---------------------------------------------------------------------------
// Fused GAT layer 1 — fully warp-independent (no block syncs).
// Block = node, warp h = head h. Per 32-edge tile:
//   - each lane loads its own edge index (coalesced)
//   - staging passes bounded by degree: ceil(n/4) passes x 4 rows (float4/8 lanes)
//   - lane = edge for scoring, lane = channel for aggregation
// ---------------------------------------------------------------------------
#define SSTR 36
__global__ void gat1_node_kernel(const float* __restrict__ att1,
                                 const float* __restrict__ b1) {
    __shared__ __align__(16) float stage[H1][32 * SSTR];
    __shared__ __align__(16) float sh_xr[H1][32];
    __shared__ __align__(16) float sh_at[H1][32];

    int d = blockIdx.x;
    int h = threadIdx.x >> 5, lane = threadIdx.x & 31;
    int off = h * CH1 + lane;
    float* S = stage[h];

    sh_at[h][lane] = att1[off];
    sh_xr[h][lane] = g_xr1[d * F1 + off];
    __syncwarp();

    int beg = g_rowptr[d], end = g_rowptr[d + 1];
    float m = -INFINITY, den = 0.f, acc = 0.f;

    // staging geometry: 8 lanes per edge-row (one float4 each), 4 rows per pass
    int erow = lane >> 3;          // 0..3
    int c4   = (lane & 7) * 4;     // 0..28
    const float* xlh = g_xl1 + h * CH1;

    for (int t = beg; t < end; t += 32) {
        int n = end - t; if (n > 32) n = 32;
        int idx = t + lane;
        int sidx = g_csrc[(idx < end) ? idx : beg];
        int np = (n + 3) >> 2;     // passes actually needed

        for (int p = 0; p < np; p++) {
            int e = p * 4 + erow;
            int se = __shfl_sync(0xFFFFFFFFu, sidx, e);
            float4 v = *(const float4*)&xlh[(size_t)se * F1 + c4];
            *(float4*)&S[e * SSTR + c4] = v;
        }
        __syncwarp();

        // score for edge 'lane'
        float p = -INFINITY;
        if (lane < n) {
            float d0 = 0.f, d1 = 0.f;
            #pragma unroll
            for (int c = 0; c < 32; c += 8) {
                float4 xv0 = *(float4*)&S[lane * SSTR + c];
                float4 xr0 = *(float4*)&sh_xr[h][c];
                float4 at0 = *(float4*)&sh_at[h][c];
                float4 xv1 = *(float4*)&S[lane * SSTR + c + 4];
                float4 xr1 = *(float4*)&sh_xr[h][c + 4];
                float4 at1 = *(float4*)&sh_at[h][c + 4];
                d0 += at0.x * leaky(xv0.x + xr0.x);
                d0 += at0.y * leaky(xv0.y + xr0.y);
                d0 += at0.z * leaky(xv0.z + xr0.z);
                d0 += at0.w * leaky(xv0.w + xr0.w);
                d1 += at1.x * leaky(xv1.x + xr1.x);
                d1 += at1.y * leaky(xv1.y + xr1.y);
                d1 += at1.z * leaky(xv1.z + xr1.z);
                d1 += at1.w * leaky(xv1.w + xr1.w);
            }
            p = d0 + d1;
        }

        // tile softmax combine
        float tmax = warpMax(p);
        float newm = fmaxf(m, tmax);
        float r = __expf(m - newm);
        den *= r; acc *= r; m = newm;
        float w = (lane < n) ? __expf(p - m) : 0.f;
        den += warpSum(w);

        // aggregate: acc(channel=lane) += sum_e w_e * S[e][lane]
        if (n == 32) {
            #pragma unroll 8
            for (int e = 0; e < 32; e++) {
                float we = __shfl_sync(0xFFFFFFFFu, w, e);
                acc += we * S[e * SSTR + lane];
            }
        } else {
            for (int e = 0; e < n; e++) {
                float we = __shfl_sync(0xFFFFFFFFu, w, e);
                acc += we * S[e * SSTR + lane];
            }
        }
        __syncwarp();
    }
    float out = acc / (den + 1e-16f) + b1[off];
    g_h1[d * F1 + off] = (out > 0.f) ? out : (__expf(out) - 1.f);
}

// ---------------------------------------------------------------------------
// Fused GAT layer 2: warp per node, lane covers channels c and c+32.
// ---------------------------------------------------------------------------
__global__ void gat2_node_kernel(const float* __restrict__ att2, int nN) {
    int d = blockIdx.x * 4 + (threadIdx.x >> 5);
    if (d >= nN) return;
    int lane = threadIdx.x & 31;
    float a0 = att2[lane], a1 = att2[32 + lane];
    float xr0 = g_xr2[d * F2 + lane];
    float xr1 = g_xr2[d * F2 + 32 + lane];
    int beg = g_rowptr[d], end = g_rowptr[d + 1];

    float mA = -INFINITY, denA = 0.f, accA0 = 0.f, accA1 = 0.f;
    float mB = -INFINITY, denB = 0.f, accB0 = 0.f, accB1 = 0.f;

    int s0 = g_csrc[beg];
    float xa0 = g_xl2[s0 * F2 + lane];
    float xa1 = g_xl2[s0 * F2 + 32 + lane];
    float xb0 = 0.f, xb1 = 0.f;
    if (beg + 1 < end) {
        int s1 = g_csrc[beg + 1];
        xb0 = g_xl2[s1 * F2 + lane];
        xb1 = g_xl2[s1 * F2 + 32 + lane];
    }

    int j = beg;
    for (; j + 1 < end; j += 2) {
        float cA0 = xa0, cA1 = xa1, cB0 = xb0, cB1 = xb1;
        if (j + 2 < end) {
            int s = g_csrc[j + 2];
            xa0 = g_xl2[s * F2 + lane];
            xa1 = g_xl2[s * F2 + 32 + lane];
        }
        if (j + 3 < end) {
            int s = g_csrc[j + 3];
            xb0 = g_xl2[s * F2 + lane];
            xb1 = g_xl2[s * F2 + 32 + lane];
        }
        float pA = warpSum(leaky(cA0 + xr0) * a0 + leaky(cA1 + xr1) * a1);
        float pB = warpSum(leaky(cB0 + xr0) * a0 + leaky(cB1 + xr1) * a1);
        if (pA > mA) { float r = __expf(mA - pA); denA *= r; accA0 *= r; accA1 *= r; mA = pA; }
        float wA = __expf(pA - mA);
        denA += wA; accA0 += wA * cA0; accA1 += wA * cA1;
        if (pB > mB) { float r = __expf(mB - pB); denB *= r; accB0 *= r; accB1 *= r; mB = pB; }
        float wB = __expf(pB - mB);
        denB += wB; accB0 += wB * cB0; accB1 += wB * cB1;
    }
    if (j < end) {
        float pA = warpSum(leaky(xa0 + xr0) * a0 + leaky(xa1 + xr1) * a1);
        if (pA > mA) { float r = __expf(mA - pA); denA *= r; accA0 *= r; accA1 *= r; mA = pA; }
        float wA = __expf(pA - mA);
        denA += wA; accA0 += wA * xa0; accA1 += wA * xa1;
    }
    float m = fmaxf(mA, mB);
    float eA = __expf(mA - m), eB = (mB == -INFINITY) ? 0.f : __expf(mB - m);
    float den = denA * eA + denB * eB;
    float inv = 1.f / (den + 1e-16f);
    g_h2[d * F2 + lane]      = (accA0 * eA + accB0 * eB) * inv;
    g_h2[d * F2 + 32 + lane] = (accA1 * eA + accB1 * eB) * inv;
}

// ---------------------------------------------------------------------------
// InstanceNorm stats: coalesced, warp-per-row-stripe, float atomics
// ---------------------------------------------------------------------------
__global__ void stats_kernel(int nN) {
    int gw = (blockIdx.x * blockDim.x + threadIdx.x) >> 5;
    int nw = (gridDim.x * blockDim.x) >> 5;
    int lane = threadIdx.x & 31;
    float s0 = 0.f, q0 = 0.f, s1 = 0.f, q1 = 0.f;
    for (int i = gw; i < nN; i += nw) {
        float v0 = g_h2[i * F2 + lane];
        float v1 = g_h2[i * F2 + 32 + lane];
        s0 += v0; q0 += v0 * v0;
        s1 += v1; q1 += v1 * v1;
    }
    atomicAdd(&g_fsum[lane], s0);
    atomicAdd(&g_fsq [lane], q0);
    atomicAdd(&g_fsum[32 + lane], s1);
    atomicAdd(&g_fsq [32 + lane], q1);
}

// ---------------------------------------------------------------------------
// Normalize + log_softmax (mean/rstd computed inline)
// ---------------------------------------------------------------------------
__global__ void finalize_kernel(const float* __restrict__ gamma,
                                const float* __restrict__ beta,
                                float* __restrict__ out, int nN) {
    int node = blockIdx.x * 4 + (threadIdx.x >> 5);
    if (node >= nN) return;
    int lane = threadIdx.x & 31;
    int c0 = lane, c1 = lane + 32;
    float invN = 1.f / (float)nN;
    float mean0 = g_fsum[c0] * invN;
    float mean1 = g_fsum[c1] * invN;
    float var0 = g_fsq[c0] * invN - mean0 * mean0;
    float var1 = g_fsq[c1] * invN - mean1 * mean1;
    float rstd0 = rsqrtf(var0 + 1e-5f);
    float rstd1 = rsqrtf(var1 + 1e-5f);
    float y0 = (g_h2[node * F2 + c0] - mean0) * rstd0 * gamma[c0] + beta[c0];
    float y1 = (g_h2[node * F2 + c1] - mean1) * rstd1 * gamma[c1] + beta[c1];
    out[node * F2 + c0] = y0;
    out[node * F2 + c1] = y1;
    float m = warpMax(fmaxf(y0, y1));
    float ssum = warpSum(expf(y0 - m) + expf(y1 - m));
    float lse = m + logf(ssum);
    float* out2 = out + (size_t)nN * F2;
    out2[node * F2 + c0] = y0 - lse;
    out2[node * F2 + c1] = y1 - lse;
}

// ---------------------------------------------------------------------------
// Launcher — CSR build forked onto side stream, overlapped with layer-1 GEMM
// ---------------------------------------------------------------------------
static cudaStream_t s_side = nullptr;
static cudaEvent_t  s_ev0 = nullptr, s_ev1 = nullptr;

extern "C" void kernel_launch(void* const* d_in, const int* in_sizes, int n_in,
                              void* d_out, int out_size) {
    const float* x     = (const float*)d_in[0];
    const float* Wl1   = (const float*)d_in[1];
    const float* Wr1   = (const float*)d_in[2];
    const float* att1  = (const float*)d_in[3];
    const float* b1    = (const float*)d_in[4];
    const float* Wl2   = (const float*)d_in[5];
    const float* Wr2   = (const float*)d_in[6];
    const float* att2  = (const float*)d_in[7];
    const float* gamma = (const float*)d_in[9];
    const float* beta  = (const float*)d_in[10];
    const int*   ei    = (const int*)d_in[11];

    int nN = in_sizes[0] / F0;
    int nE = in_sizes[11] / 2;
    int nET = nE + nN;
    const int* src = ei;
    const int* dst = ei + nE;

    if (s_side == nullptr) {
        cudaStreamCreateWithFlags(&s_side, cudaStreamNonBlocking);
        cudaEventCreateWithFlags(&s_ev0, cudaEventDisableTiming);
        cudaEventCreateWithFlags(&s_ev1, cudaEventDisableTiming);
    }

    float *xl1, *xr1, *h1, *xl2, *xr2;
    cudaGetSymbolAddress((void**)&xl1, g_xl1);
    cudaGetSymbolAddress((void**)&xr1, g_xr1);
    cudaGetSymbolAddress((void**)&h1,  g_h1);
    cudaGetSymbolAddress((void**)&xl2, g_xl2);
    cudaGetSymbolAddress((void**)&xr2, g_xr2);

    // Fork: CSR build on side stream
    cudaEventRecord(s_ev0, 0);
    cudaStreamWaitEvent(s_side, s_ev0, 0);
    zero_deg_kernel<<<(nN + 255) / 256, 256, 0, s_side>>>(nN);
    hist_kernel<<<(nET + 255) / 256, 256, 0, s_side>>>(dst, nE, nET);
    scan_kernel<<<1, 1024, 0, s_side>>>(nN);
    scatter_kernel<<<(nET + 255) / 256, 256, 0, s_side>>>(src, dst, nE, nET);
    cudaEventRecord(s_ev1, s_side);

    // Main: layer-1 GEMMs concurrent with CSR
    {
        dim3 grid(F1 / 64, (nN + 127) / 128, 2);
        mma_gemm2_kernel<<<grid, 256>>>(x, Wl1, Wr1, xl1, xr1, nN, F0, F1);
    }
    // Join
    cudaStreamWaitEvent(0, s_ev1, 0);

    gat1_node_kernel<<<nN, 256>>>(att1, b1);

    {
        dim3 grid(F2 / 64, (nN + 127) / 128, 2);
        mma_gemm2_kernel<<<grid, 256>>>(h1, Wl2, Wr2, xl2, xr2, nN, F1, F2);
    }
    gat2_node_kernel<<<(nN + 3) / 4, 128>>>(att2, nN);

    stats_kernel<<<64, 256>>>(nN);
    finalize_kernel<<<(nN + 3) / 4, 128>>>(gamma, beta, (float*)d_out, nN);
}

// round 9
// speedup vs baseline: 5.0085x; 1.0626x over previous
#include <cuda_runtime.h>
#include <math.h>

#define MAXN 20000
#define MAXE 320000
#define MAXET (MAXE + MAXN)
#define H1 8
#define CH1 32
#define F1 256
#define F0 128
#define F2 64

// ---------------------------------------------------------------------------
// Scratch
// ---------------------------------------------------------------------------
__device__ float g_xl1[MAXN * F1];
__device__ float g_xr1[MAXN * F1];
__device__ float g_h1 [MAXN * F1];
__device__ float g_xl2[MAXN * F2];
__device__ float g_xr2[MAXN * F2];
__device__ float g_h2 [MAXN * F2];

__device__ int g_deg[MAXN];
__device__ int g_rowptr[MAXN + 1];
__device__ int g_cursor[MAXN];
__device__ int g_csrc[MAXET];

__device__ float g_fsum[F2];
__device__ float g_fsq [F2];

// ---------------------------------------------------------------------------
// Helpers
// ---------------------------------------------------------------------------
__device__ __forceinline__ float warpSum(float v) {
    #pragma unroll
    for (int o = 16; o > 0; o >>= 1) v += __shfl_xor_sync(0xFFFFFFFFu, v, o);
    return v;
}
__device__ __forceinline__ float warpMax(float v) {
    #pragma unroll
    for (int o = 16; o > 0; o >>= 1) v = fmaxf(v, __shfl_xor_sync(0xFFFFFFFFu, v, o));
    return v;
}
__device__ __forceinline__ float f2tf32f(float x) {
    unsigned u;
    asm("cvt.rna.tf32.f32 %0, %1;" : "=r"(u) : "f"(x));
    return __uint_as_float(u);
}
__device__ __forceinline__ float leaky(float v) { return fmaxf(v, 0.2f * v); }

// ---------------------------------------------------------------------------
// CSR build (side stream, overlapped with layer-1 GEMM)
// ---------------------------------------------------------------------------
__global__ void zero_deg_kernel(int nN) {
    int i = blockIdx.x * blockDim.x + threadIdx.x;
    if (i < nN) g_deg[i] = 0;
    if (i < F2) { g_fsum[i] = 0.f; g_fsq[i] = 0.f; }
}

__global__ void hist_kernel(const int* __restrict__ dst, int nE, int nET) {
    int i = blockIdx.x * blockDim.x + threadIdx.x;
    if (i >= nET) return;
    int d = (i < nE) ? dst[i] : i - nE;
    atomicAdd(&g_deg[d], 1);
}

#define SCAN_CHUNK 20
__global__ void scan_kernel(int nN) {
    __shared__ int sh[1024];
    int tid = threadIdx.x;
    int start = tid * SCAN_CHUNK;
    int cnt = nN - start;
    if (cnt < 0) cnt = 0;
    if (cnt > SCAN_CHUNK) cnt = SCAN_CHUNK;
    int vals[SCAN_CHUNK];
    int sum = 0;
    for (int i = 0; i < cnt; i++) { vals[i] = g_deg[start + i]; sum += vals[i]; }
    sh[tid] = sum;
    __syncthreads();
    #pragma unroll
    for (int o = 1; o < 1024; o <<= 1) {
        int t = (tid >= o) ? sh[tid - o] : 0;
        __syncthreads();
        sh[tid] += t;
        __syncthreads();
    }
    int run = sh[tid] - sum;
    for (int i = 0; i < cnt; i++) {
        g_rowptr[start + i] = run;
        g_cursor[start + i] = run;
        run += vals[i];
    }
    if (tid == 1023) g_rowptr[nN] = sh[1023];
}

__global__ void scatter_kernel(const int* __restrict__ src,
                               const int* __restrict__ dst, int nE, int nET) {
    int i = blockIdx.x * blockDim.x + threadIdx.x;
    if (i >= nET) return;
    int s, d;
    if (i < nE) { s = src[i]; d = dst[i]; } else { s = d = i - nE; }
    int slot = atomicAdd(&g_cursor[d], 1);
    g_csrc[slot] = s;
}

// ---------------------------------------------------------------------------
// Pipelined TF32 GEMM: BM=128, BN=64, BK=16, 256 threads (8 warps, 4x2).
// ---------------------------------------------------------------------------
#define PADA 20
#define PADB 72
__global__ void __launch_bounds__(256, 2)
mma_gemm2_kernel(const float* __restrict__ Amat,
                 const float* __restrict__ Bl,
                 const float* __restrict__ Br,
                 float* __restrict__ outL,
                 float* __restrict__ outR,
                 int Mdim, int Kdim, int Ndim) {
    const float* Bmat = blockIdx.z ? Br : Bl;
    float*       Cmat = blockIdx.z ? outR : outL;
    __shared__ __align__(16) float As[2][128][PADA];
    __shared__ __align__(16) float Bs[2][16][PADB];
    int tid = threadIdx.x;
    int lane = tid & 31, warp = tid >> 5;
    int wm = warp >> 1, wn = warp & 1;
    int g = lane >> 2, tg = lane & 3;
    int row0 = blockIdx.y * 128, col0 = blockIdx.x * 64;

    int ar0 = tid >> 2, ac = (tid & 3) * 4;
    int br = tid >> 4, bc = (tid & 15) * 4;

    float4 ra[2], rb;

    float acc[2][4][4];
    #pragma unroll
    for (int i = 0; i < 2; i++)
        #pragma unroll
        for (int j = 0; j < 4; j++)
            #pragma unroll
            for (int k = 0; k < 4; k++) acc[i][j][k] = 0.f;

    int nit = Kdim / 16;

    #pragma unroll
    for (int i = 0; i < 2; i++) {
        int gr = row0 + ar0 + i * 64;
        ra[i] = (gr < Mdim) ? *(const float4*)&Amat[(size_t)gr * Kdim + ac]
                            : make_float4(0.f, 0.f, 0.f, 0.f);
    }
    rb = *(const float4*)&Bmat[(size_t)br * Ndim + col0 + bc];
    #pragma unroll
    for (int i = 0; i < 2; i++) {
        int r = ar0 + i * 64;
        As[0][r][ac + 0] = f2tf32f(ra[i].x);
        As[0][r][ac + 1] = f2tf32f(ra[i].y);
        As[0][r][ac + 2] = f2tf32f(ra[i].z);
        As[0][r][ac + 3] = f2tf32f(ra[i].w);
    }
    Bs[0][br][bc + 0] = f2tf32f(rb.x);
    Bs[0][br][bc + 1] = f2tf32f(rb.y);
    Bs[0][br][bc + 2] = f2tf32f(rb.z);
    Bs[0][br][bc + 3] = f2tf32f(rb.w);
    __syncthreads();

    for (int it = 0; it < nit; it++) {
        int k0n = (it + 1) * 16;
        bool more = (it + 1) < nit;
        if (more) {
            #pragma unroll
            for (int i = 0; i < 2; i++) {
                int gr = row0 + ar0 + i * 64;
                ra[i] = (gr < Mdim) ? *(const float4*)&Amat[(size_t)gr * Kdim + k0n + ac]
                                    : make_float4(0.f, 0.f, 0.f, 0.f);
            }
            rb = *(const float4*)&Bmat[(size_t)(k0n + br) * Ndim + col0 + bc];
        }
        int cb = it & 1;
        #pragma unroll
        for (int kk = 0; kk < 16; kk += 8) {
            unsigned a[2][4], b[4][2];
            #pragma unroll
            for (int mt = 0; mt < 2; mt++) {
                int r = wm * 32 + mt * 16;
                a[mt][0] = __float_as_uint(As[cb][r + g][kk + tg]);
                a[mt][1] = __float_as_uint(As[cb][r + g + 8][kk + tg]);
                a[mt][2] = __float_as_uint(As[cb][r + g][kk + tg + 4]);
                a[mt][3] = __float_as_uint(As[cb][r + g + 8][kk + tg + 4]);
            }
            #pragma unroll
            for (int nt = 0; nt < 4; nt++) {
                int c = wn * 32 + nt * 8 + g;
                b[nt][0] = __float_as_uint(Bs[cb][kk + tg][c]);
                b[nt][1] = __float_as_uint(Bs[cb][kk + tg + 4][c]);
            }
            #pragma unroll
            for (int mt = 0; mt < 2; mt++)
                #pragma unroll
                for (int nt = 0; nt < 4; nt++) {
                    asm volatile(
                        "mma.sync.aligned.m16n8k8.row.col.f32.tf32.tf32.f32 "
                        "{%0,%1,%2,%3}, {%4,%5,%6,%7}, {%8,%9}, {%0,%1,%2,%3};\n"
                        : "+f"(acc[mt][nt][0]), "+f"(acc[mt][nt][1]),
                          "+f"(acc[mt][nt][2]), "+f"(acc[mt][nt][3])
                        : "r"(a[mt][0]), "r"(a[mt][1]), "r"(a[mt][2]), "r"(a[mt][3]),
                          "r"(b[nt][0]), "r"(b[nt][1]));
                }
        }
        if (more) {
            __syncthreads();
            int sb = (it + 1) & 1;
            #pragma unroll
            for (int i = 0; i < 2; i++) {
                int r = ar0 + i * 64;
                As[sb][r][ac + 0] = f2tf32f(ra[i].x);
                As[sb][r][ac + 1] = f2tf32f(ra[i].y);
                As[sb][r][ac + 2] = f2tf32f(ra[i].z);
                As[sb][r][ac + 3] = f2tf32f(ra[i].w);
            }
            Bs[sb][br][bc + 0] = f2tf32f(rb.x);
            Bs[sb][br][bc + 1] = f2tf32f(rb.y);
            Bs[sb][br][bc + 2] = f2tf32f(rb.z);
            Bs[sb][br][bc + 3] = f2tf32f(rb.w);
            __syncthreads();
        }
    }
    #pragma unroll
    for (int mt = 0; mt < 2; mt++) {
        int rbase = row0 + wm * 32 + mt * 16;
        #pragma unroll
        for (int nt = 0; nt < 4; nt++) {
            int c = col0 + wn * 32 + nt * 8 + tg * 2;
            int r = rbase + g;
            if (r < Mdim) *(float2*)&Cmat[(size_t)r * Ndim + c] =
                make_float2(acc[mt][nt][0], acc[mt][nt][1]);
            r = rbase + g + 8;
            if (r < Mdim) *(float2*)&Cmat[(size_t)r * Ndim + c] =
                make_float2(acc[mt][nt][2], acc[mt][nt][3]);
        }
    }
}

// ---------------------------------------------------------------------------
// Fused GAT layer 1 — warp-independent, no-max softmax, S2 = xl + xr staging.
// Aggregation identity: sum_e alpha_e * xl_e = (sum_e w_e*S2_e - den*xr)/den.
// ---------------------------------------------------------------------------
#define SSTR 36
__global__ void gat1_node_kernel(const float* __restrict__ att1,
                                 const float* __restrict__ b1) {
    __shared__ __align__(16) float stage[H1][32 * SSTR];
    __shared__ __align__(16) float sh_xr[H1][32];
    __shared__ __align__(16) float sh_at[H1][32];

    int d = blockIdx.x;
    int h = threadIdx.x >> 5, lane = threadIdx.x & 31;
    int off = h * CH1 + lane;
    float* S = stage[h];

    sh_at[h][lane] = att1[off];
    float xr_l = g_xr1[d * F1 + off];
    sh_xr[h][lane] = xr_l;
    __syncwarp();

    int beg = g_rowptr[d], end = g_rowptr[d + 1];
    float den = 0.f;
    float acc0 = 0.f, acc1 = 0.f, acc2 = 0.f, acc3 = 0.f;

    // staging geometry: 8 lanes per edge-row (one float4 each), 4 rows per pass
    int erow = lane >> 3;          // 0..3
    int c4   = (lane & 7) * 4;     // 0..28
    float4 xr4 = *(float4*)&sh_xr[h][c4];
    const float* xlh = g_xl1 + h * CH1;

    for (int t = beg; t < end; t += 32) {
        int n = end - t; if (n > 32) n = 32;
        int idx = t + lane;
        int sidx = g_csrc[(idx < end) ? idx : beg];
        int np = (n + 3) >> 2;

        for (int p = 0; p < np; p++) {
            int e = p * 4 + erow;
            int se = __shfl_sync(0xFFFFFFFFu, sidx, e);
            float4 v = *(const float4*)&xlh[(size_t)se * F1 + c4];
            v.x += xr4.x; v.y += xr4.y; v.z += xr4.z; v.w += xr4.w;
            *(float4*)&S[e * SSTR + c4] = v;
        }
        __syncwarp();

        // score for edge 'lane' (no max subtraction)
        float w = 0.f;
        if (lane < n) {
            float d0 = 0.f, d1 = 0.f;
            #pragma unroll
            for (int c = 0; c < 32; c += 8) {
                float4 xv0 = *(float4*)&S[lane * SSTR + c];
                float4 at0 = *(float4*)&sh_at[h][c];
                float4 xv1 = *(float4*)&S[lane * SSTR + c + 4];
                float4 at1 = *(float4*)&sh_at[h][c + 4];
                d0 += at0.x * leaky(xv0.x);
                d0 += at0.y * leaky(xv0.y);
                d0 += at0.z * leaky(xv0.z);
                d0 += at0.w * leaky(xv0.w);
                d1 += at1.x * leaky(xv1.x);
                d1 += at1.y * leaky(xv1.y);
                d1 += at1.z * leaky(xv1.z);
                d1 += at1.w * leaky(xv1.w);
            }
            w = __expf(d0 + d1);
        }
        den += warpSum(w);

        // aggregate S2: 4 independent accumulator chains
        int e = 0;
        for (; e + 3 < n; e += 4) {
            float w0 = __shfl_sync(0xFFFFFFFFu, w, e);
            float w1 = __shfl_sync(0xFFFFFFFFu, w, e + 1);
            float w2 = __shfl_sync(0xFFFFFFFFu, w, e + 2);
            float w3 = __shfl_sync(0xFFFFFFFFu, w, e + 3);
            acc0 += w0 * S[(e    ) * SSTR + lane];
            acc1 += w1 * S[(e + 1) * SSTR + lane];
            acc2 += w2 * S[(e + 2) * SSTR + lane];
            acc3 += w3 * S[(e + 3) * SSTR + lane];
        }
        for (; e < n; e++) {
            float we = __shfl_sync(0xFFFFFFFFu, w, e);
            acc0 += we * S[e * SSTR + lane];
        }
        __syncwarp();
    }
    float inv = 1.f / (den + 1e-16f);
    float out = ((acc0 + acc1) + (acc2 + acc3) - den * xr_l) * inv + b1[off];
    g_h1[d * F1 + off] = (out > 0.f) ? out : (__expf(out) - 1.f);
}

// ---------------------------------------------------------------------------
// Fused GAT layer 2: warp per node, lane covers channels c and c+32.
// 2-edge interleaved chains, no-max softmax.
// ---------------------------------------------------------------------------
__global__ void gat2_node_kernel(const float* __restrict__ att2, int nN) {
    int d = blockIdx.x * 4 + (threadIdx.x >> 5);
    if (d >= nN) return;
    int lane = threadIdx.x & 31;
    float a0 = att2[lane], a1 = att2[32 + lane];
    float xr0 = g_xr2[d * F2 + lane];
    float xr1 = g_xr2[d * F2 + 32 + lane];
    int beg = g_rowptr[d], end = g_rowptr[d + 1];

    float denA = 0.f, accA0 = 0.f, accA1 = 0.f;
    float denB = 0.f, accB0 = 0.f, accB1 = 0.f;

    int s0 = g_csrc[beg];
    float xa0 = g_xl2[s0 * F2 + lane];
    float xa1 = g_xl2[s0 * F2 + 32 + lane];
    float xb0 = 0.f, xb1 = 0.f;
    if (beg + 1 < end) {
        int s1 = g_csrc[beg + 1];
        xb0 = g_xl2[s1 * F2 + lane];
        xb1 = g_xl2[s1 * F2 + 32 + lane];
    }

    int j = beg;
    for (; j + 1 < end; j += 2) {
        float cA0 = xa0, cA1 = xa1, cB0 = xb0, cB1 = xb1;
        if (j + 2 < end) {
            int s = g_csrc[j + 2];
            xa0 = g_xl2[s * F2 + lane];
            xa1 = g_xl2[s * F2 + 32 + lane];
        }
        if (j + 3 < end) {
            int s = g_csrc[j + 3];
            xb0 = g_xl2[s * F2 + lane];
            xb1 = g_xl2[s * F2 + 32 + lane];
        }
        float pA = warpSum(leaky(cA0 + xr0) * a0 + leaky(cA1 + xr1) * a1);
        float pB = warpSum(leaky(cB0 + xr0) * a0 + leaky(cB1 + xr1) * a1);
        float wA = __expf(pA);
        denA += wA; accA0 += wA * cA0; accA1 += wA * cA1;
        float wB = __expf(pB);
        denB += wB; accB0 += wB * cB0; accB1 += wB * cB1;
    }
    if (j < end) {
        float pA = warpSum(leaky(xa0 + xr0) * a0 + leaky(xa1 + xr1) * a1);
        float wA = __expf(pA);
        denA += wA; accA0 += wA * xa0; accA1 += wA * xa1;
    }
    float inv = 1.f / (denA + denB + 1e-16f);
    g_h2[d * F2 + lane]      = (accA0 + accB0) * inv;
    g_h2[d * F2 + 32 + lane] = (accA1 + accB1) * inv;
}

// ---------------------------------------------------------------------------
// InstanceNorm stats: coalesced, warp-per-row-stripe, float atomics
// ---------------------------------------------------------------------------
__global__ void stats_kernel(int nN) {
    int gw = (blockIdx.x * blockDim.x + threadIdx.x) >> 5;
    int nw = (gridDim.x * blockDim.x) >> 5;
    int lane = threadIdx.x & 31;
    float s0 = 0.f, q0 = 0.f, s1 = 0.f, q1 = 0.f;
    for (int i = gw; i < nN; i += nw) {
        float v0 = g_h2[i * F2 + lane];
        float v1 = g_h2[i * F2 + 32 + lane];
        s0 += v0; q0 += v0 * v0;
        s1 += v1; q1 += v1 * v1;
    }
    atomicAdd(&g_fsum[lane], s0);
    atomicAdd(&g_fsq [lane], q0);
    atomicAdd(&g_fsum[32 + lane], s1);
    atomicAdd(&g_fsq [32 + lane], q1);
}

// ---------------------------------------------------------------------------
// Normalize + log_softmax (mean/rstd computed inline)
// ---------------------------------------------------------------------------
__global__ void finalize_kernel(const float* __restrict__ gamma,
                                const float* __restrict__ beta,
                                float* __restrict__ out, int nN) {
    int node = blockIdx.x * 4 + (threadIdx.x >> 5);
    if (node >= nN) return;
    int lane = threadIdx.x & 31;
    int c0 = lane, c1 = lane + 32;
    float invN = 1.f / (float)nN;
    float mean0 = g_fsum[c0] * invN;
    float mean1 = g_fsum[c1] * invN;
    float var0 = g_fsq[c0] * invN - mean0 * mean0;
    float var1 = g_fsq[c1] * invN - mean1 * mean1;
    float rstd0 = rsqrtf(var0 + 1e-5f);
    float rstd1 = rsqrtf(var1 + 1e-5f);
    float y0 = (g_h2[node * F2 + c0] - mean0) * rstd0 * gamma[c0] + beta[c0];
    float y1 = (g_h2[node * F2 + c1] - mean1) * rstd1 * gamma[c1] + beta[c1];
    out[node * F2 + c0] = y0;
    out[node * F2 + c1] = y1;
    float m = warpMax(fmaxf(y0, y1));
    float ssum = warpSum(expf(y0 - m) + expf(y1 - m));
    float lse = m + logf(ssum);
    float* out2 = out + (size_t)nN * F2;
    out2[node * F2 + c0] = y0 - lse;
    out2[node * F2 + c1] = y1 - lse;
}

// ---------------------------------------------------------------------------
// Launcher — CSR build forked onto side stream, overlapped with layer-1 GEMM
// ---------------------------------------------------------------------------
static cudaStream_t s_side = nullptr;
static cudaEvent_t  s_ev0 = nullptr, s_ev1 = nullptr;

extern "C" void kernel_launch(void* const* d_in, const int* in_sizes, int n_in,
                              void* d_out, int out_size) {
    const float* x     = (const float*)d_in[0];
    const float* Wl1   = (const float*)d_in[1];
    const float* Wr1   = (const float*)d_in[2];
    const float* att1  = (const float*)d_in[3];
    const float* b1    = (const float*)d_in[4];
    const float* Wl2   = (const float*)d_in[5];
    const float* Wr2   = (const float*)d_in[6];
    const float* att2  = (const float*)d_in[7];
    const float* gamma = (const float*)d_in[9];
    const float* beta  = (const float*)d_in[10];
    const int*   ei    = (const int*)d_in[11];

    int nN = in_sizes[0] / F0;
    int nE = in_sizes[11] / 2;
    int nET = nE + nN;
    const int* src = ei;
    const int* dst = ei + nE;

    if (s_side == nullptr) {
        cudaStreamCreateWithFlags(&s_side, cudaStreamNonBlocking);
        cudaEventCreateWithFlags(&s_ev0, cudaEventDisableTiming);
        cudaEventCreateWithFlags(&s_ev1, cudaEventDisableTiming);
    }

    float *xl1, *xr1, *h1, *xl2, *xr2;
    cudaGetSymbolAddress((void**)&xl1, g_xl1);
    cudaGetSymbolAddress((void**)&xr1, g_xr1);
    cudaGetSymbolAddress((void**)&h1,  g_h1);
    cudaGetSymbolAddress((void**)&xl2, g_xl2);
    cudaGetSymbolAddress((void**)&xr2, g_xr2);

    // Fork: CSR build on side stream
    cudaEventRecord(s_ev0, 0);
    cudaStreamWaitEvent(s_side, s_ev0, 0);
    zero_deg_kernel<<<(nN + 255) / 256, 256, 0, s_side>>>(nN);
    hist_kernel<<<(nET + 255) / 256, 256, 0, s_side>>>(dst, nE, nET);
    scan_kernel<<<1, 1024, 0, s_side>>>(nN);
    scatter_kernel<<<(nET + 255) / 256, 256, 0, s_side>>>(src, dst, nE, nET);
    cudaEventRecord(s_ev1, s_side);

    // Main: layer-1 GEMMs concurrent with CSR
    {
        dim3 grid(F1 / 64, (nN + 127) / 128, 2);
        mma_gemm2_kernel<<<grid, 256>>>(x, Wl1, Wr1, xl1, xr1, nN, F0, F1);
    }
    // Join
    cudaStreamWaitEvent(0, s_ev1, 0);

    gat1_node_kernel<<<nN, 256>>>(att1, b1);

    {
        dim3 grid(F2 / 64, (nN + 127) / 128, 2);
        mma_gemm2_kernel<<<grid, 256>>>(h1, Wl2, Wr2, xl2, xr2, nN, F1, F2);
    }
    gat2_node_kernel<<<(nN + 3) / 4, 128>>>(att2, nN);

    stats_kernel<<<64, 256>>>(nN);
    finalize_kernel<<<(nN + 3) / 4, 128>>>(gamma, beta, (float*)d_out, nN);
}

// round 10
// speedup vs baseline: 5.6380x; 1.1257x over previous
#include <cuda_runtime.h>
#include <math.h>

#define MAXN 20000
#define MAXE 320000
#define MAXET (MAXE + MAXN)
#define H1 8
#define CH1 32
#define F1 256
#define F0 128
#define F2 64

// ---------------------------------------------------------------------------
// Scratch
// ---------------------------------------------------------------------------
__device__ float g_xl1[MAXN * F1];
__device__ float g_xr1[MAXN * F1];
__device__ float g_h1 [MAXN * F1];
__device__ float g_xl2[MAXN * F2];
__device__ float g_xr2[MAXN * F2];
__device__ float g_h2 [MAXN * F2];

__device__ int g_deg[MAXN];
__device__ int g_rowptr[MAXN + 1];
__device__ int g_cursor[MAXN];
__device__ int g_csrc[MAXET];

__device__ float g_fsum[F2];
__device__ float g_fsq [F2];

// ---------------------------------------------------------------------------
// Helpers
// ---------------------------------------------------------------------------
__device__ __forceinline__ float warpSum(float v) {
    #pragma unroll
    for (int o = 16; o > 0; o >>= 1) v += __shfl_xor_sync(0xFFFFFFFFu, v, o);
    return v;
}
__device__ __forceinline__ float warpMax(float v) {
    #pragma unroll
    for (int o = 16; o > 0; o >>= 1) v = fmaxf(v, __shfl_xor_sync(0xFFFFFFFFu, v, o));
    return v;
}
__device__ __forceinline__ float f2tf32f(float x) {
    unsigned u;
    asm("cvt.rna.tf32.f32 %0, %1;" : "=r"(u) : "f"(x));
    return __uint_as_float(u);
}
__device__ __forceinline__ float leaky(float v) { return fmaxf(v, 0.2f * v); }

// ---------------------------------------------------------------------------
// CSR build (side stream, overlapped with layer-1 GEMM)
// ---------------------------------------------------------------------------
__global__ void zero_deg_kernel(int nN) {
    int i = blockIdx.x * blockDim.x + threadIdx.x;
    if (i < nN) g_deg[i] = 0;
    if (i < F2) { g_fsum[i] = 0.f; g_fsq[i] = 0.f; }
}

__global__ void hist_kernel(const int* __restrict__ dst, int nE, int nET) {
    int i = blockIdx.x * blockDim.x + threadIdx.x;
    if (i >= nET) return;
    int d = (i < nE) ? dst[i] : i - nE;
    atomicAdd(&g_deg[d], 1);
}

#define SCAN_CHUNK 20
__global__ void scan_kernel(int nN) {
    __shared__ int sh[1024];
    int tid = threadIdx.x;
    int start = tid * SCAN_CHUNK;
    int cnt = nN - start;
    if (cnt < 0) cnt = 0;
    if (cnt > SCAN_CHUNK) cnt = SCAN_CHUNK;
    int vals[SCAN_CHUNK];
    int sum = 0;
    for (int i = 0; i < cnt; i++) { vals[i] = g_deg[start + i]; sum += vals[i]; }
    sh[tid] = sum;
    __syncthreads();
    #pragma unroll
    for (int o = 1; o < 1024; o <<= 1) {
        int t = (tid >= o) ? sh[tid - o] : 0;
        __syncthreads();
        sh[tid] += t;
        __syncthreads();
    }
    int run = sh[tid] - sum;
    for (int i = 0; i < cnt; i++) {
        g_rowptr[start + i] = run;
        g_cursor[start + i] = run;
        run += vals[i];
    }
    if (tid == 1023) g_rowptr[nN] = sh[1023];
}

__global__ void scatter_kernel(const int* __restrict__ src,
                               const int* __restrict__ dst, int nE, int nET) {
    int i = blockIdx.x * blockDim.x + threadIdx.x;
    if (i >= nET) return;
    int s, d;
    if (i < nE) { s = src[i]; d = dst[i]; } else { s = d = i - nE; }
    int slot = atomicAdd(&g_cursor[d], 1);
    g_csrc[slot] = s;
}

// ---------------------------------------------------------------------------
// Pipelined TF32 GEMM: BM=128, BN=64, BK=16, 256 threads (8 warps, 4x2).
// ---------------------------------------------------------------------------
#define PADA 20
#define PADB 72
__global__ void __launch_bounds__(256, 2)
mma_gemm2_kernel(const float* __restrict__ Amat,
                 const float* __restrict__ Bl,
                 const float* __restrict__ Br,
                 float* __restrict__ outL,
                 float* __restrict__ outR,
                 int Mdim, int Kdim, int Ndim) {
    const float* Bmat = blockIdx.z ? Br : Bl;
    float*       Cmat = blockIdx.z ? outR : outL;
    __shared__ __align__(16) float As[2][128][PADA];
    __shared__ __align__(16) float Bs[2][16][PADB];
    int tid = threadIdx.x;
    int lane = tid & 31, warp = tid >> 5;
    int wm = warp >> 1, wn = warp & 1;
    int g = lane >> 2, tg = lane & 3;
    int row0 = blockIdx.y * 128, col0 = blockIdx.x * 64;

    int ar0 = tid >> 2, ac = (tid & 3) * 4;
    int br = tid >> 4, bc = (tid & 15) * 4;

    float4 ra[2], rb;

    float acc[2][4][4];
    #pragma unroll
    for (int i = 0; i < 2; i++)
        #pragma unroll
        for (int j = 0; j < 4; j++)
            #pragma unroll
            for (int k = 0; k < 4; k++) acc[i][j][k] = 0.f;

    int nit = Kdim / 16;

    #pragma unroll
    for (int i = 0; i < 2; i++) {
        int gr = row0 + ar0 + i * 64;
        ra[i] = (gr < Mdim) ? *(const float4*)&Amat[(size_t)gr * Kdim + ac]
                            : make_float4(0.f, 0.f, 0.f, 0.f);
    }
    rb = *(const float4*)&Bmat[(size_t)br * Ndim + col0 + bc];
    #pragma unroll
    for (int i = 0; i < 2; i++) {
        int r = ar0 + i * 64;
        As[0][r][ac + 0] = f2tf32f(ra[i].x);
        As[0][r][ac + 1] = f2tf32f(ra[i].y);
        As[0][r][ac + 2] = f2tf32f(ra[i].z);
        As[0][r][ac + 3] = f2tf32f(ra[i].w);
    }
    Bs[0][br][bc + 0] = f2tf32f(rb.x);
    Bs[0][br][bc + 1] = f2tf32f(rb.y);
    Bs[0][br][bc + 2] = f2tf32f(rb.z);
    Bs[0][br][bc + 3] = f2tf32f(rb.w);
    __syncthreads();

    for (int it = 0; it < nit; it++) {
        int k0n = (it + 1) * 16;
        bool more = (it + 1) < nit;
        if (more) {
            #pragma unroll
            for (int i = 0; i < 2; i++) {
                int gr = row0 + ar0 + i * 64;
                ra[i] = (gr < Mdim) ? *(const float4*)&Amat[(size_t)gr * Kdim + k0n + ac]
                                    : make_float4(0.f, 0.f, 0.f, 0.f);
            }
            rb = *(const float4*)&Bmat[(size_t)(k0n + br) * Ndim + col0 + bc];
        }
        int cb = it & 1;
        #pragma unroll
        for (int kk = 0; kk < 16; kk += 8) {
            unsigned a[2][4], b[4][2];
            #pragma unroll
            for (int mt = 0; mt < 2; mt++) {
                int r = wm * 32 + mt * 16;
                a[mt][0] = __float_as_uint(As[cb][r + g][kk + tg]);
                a[mt][1] = __float_as_uint(As[cb][r + g + 8][kk + tg]);
                a[mt][2] = __float_as_uint(As[cb][r + g][kk + tg + 4]);
                a[mt][3] = __float_as_uint(As[cb][r + g + 8][kk + tg + 4]);
            }
            #pragma unroll
            for (int nt = 0; nt < 4; nt++) {
                int c = wn * 32 + nt * 8 + g;
                b[nt][0] = __float_as_uint(Bs[cb][kk + tg][c]);
                b[nt][1] = __float_as_uint(Bs[cb][kk + tg + 4][c]);
            }
            #pragma unroll
            for (int mt = 0; mt < 2; mt++)
                #pragma unroll
                for (int nt = 0; nt < 4; nt++) {
                    asm volatile(
                        "mma.sync.aligned.m16n8k8.row.col.f32.tf32.tf32.f32 "
                        "{%0,%1,%2,%3}, {%4,%5,%6,%7}, {%8,%9}, {%0,%1,%2,%3};\n"
                        : "+f"(acc[mt][nt][0]), "+f"(acc[mt][nt][1]),
                          "+f"(acc[mt][nt][2]), "+f"(acc[mt][nt][3])
                        : "r"(a[mt][0]), "r"(a[mt][1]), "r"(a[mt][2]), "r"(a[mt][3]),
                          "r"(b[nt][0]), "r"(b[nt][1]));
                }
        }
        if (more) {
            __syncthreads();
            int sb = (it + 1) & 1;
            #pragma unroll
            for (int i = 0; i < 2; i++) {
                int r = ar0 + i * 64;
                As[sb][r][ac + 0] = f2tf32f(ra[i].x);
                As[sb][r][ac + 1] = f2tf32f(ra[i].y);
                As[sb][r][ac + 2] = f2tf32f(ra[i].z);
                As[sb][r][ac + 3] = f2tf32f(ra[i].w);
            }
            Bs[sb][br][bc + 0] = f2tf32f(rb.x);
            Bs[sb][br][bc + 1] = f2tf32f(rb.y);
            Bs[sb][br][bc + 2] = f2tf32f(rb.z);
            Bs[sb][br][bc + 3] = f2tf32f(rb.w);
            __syncthreads();
        }
    }
    #pragma unroll
    for (int mt = 0; mt < 2; mt++) {
        int rbase = row0 + wm * 32 + mt * 16;
        #pragma unroll
        for (int nt = 0; nt < 4; nt++) {
            int c = col0 + wn * 32 + nt * 8 + tg * 2;
            int r = rbase + g;
            if (r < Mdim) *(float2*)&Cmat[(size_t)r * Ndim + c] =
                make_float2(acc[mt][nt][0], acc[mt][nt][1]);
            r = rbase + g + 8;
            if (r < Mdim) *(float2*)&Cmat[(size_t)r * Ndim + c] =
                make_float2(acc[mt][nt][2], acc[mt][nt][3]);
        }
    }
}

// ---------------------------------------------------------------------------
// Fused GAT layer 1 — register-only (no shared memory, no syncs).
// Block = node, warp h = head h. Lane layout: grp = lane&7 owns channels
// 4*grp..4*grp+3; erow = lane>>3 selects edge within a 4-edge pass.
// Per pass: 8-lane group gathers one full edge row (LDG.128 x8 = 128B),
// dot-partial -> 3-step butterfly -> w = exp(score) -> acc4 += w*S2.
// End: butterfly over erow (xor 8,16), lanes 0..7 write float4.
// Identity: sum_e alpha_e*xl_e = (acc - den*xr)/den.
// ---------------------------------------------------------------------------
__global__ void gat1_node_kernel(const float* __restrict__ att1,
                                 const float* __restrict__ b1) {
    int d = blockIdx.x;
    int h = threadIdx.x >> 5, lane = threadIdx.x & 31;
    int grp = lane & 7, erow = lane >> 3;
    int c4 = grp * 4;

    float4 at4 = *(const float4*)&att1[h * CH1 + c4];
    float4 xr4 = *(const float4*)&g_xr1[d * F1 + h * CH1 + c4];
    const float* xlh = g_xl1 + h * CH1;

    int beg = g_rowptr[d], end = g_rowptr[d + 1];
    float den = 0.f;
    float4 acc = make_float4(0.f, 0.f, 0.f, 0.f);

    for (int t = beg; t < end; t += 32) {
        int n = end - t; if (n > 32) n = 32;
        int idx = t + lane;
        int sidx = g_csrc[(idx < end) ? idx : beg];
        int np = (n + 3) >> 2;

        // 2-stage pipeline: prefetch pass p+1's row while computing pass p
        int se = __shfl_sync(0xFFFFFFFFu, sidx, erow);
        float4 v = *(const float4*)&xlh[(size_t)se * F1 + c4];

        for (int p = 0; p < np; p++) {
            float4 cur = v;
            if (p + 1 < np) {
                int se2 = __shfl_sync(0xFFFFFFFFu, sidx, (p + 1) * 4 + erow);
                v = *(const float4*)&xlh[(size_t)se2 * F1 + c4];
            }
            int e = p * 4 + erow;
            cur.x += xr4.x; cur.y += xr4.y; cur.z += xr4.z; cur.w += xr4.w;
            float pl = at4.x * leaky(cur.x) + at4.y * leaky(cur.y)
                     + at4.z * leaky(cur.z) + at4.w * leaky(cur.w);
            pl += __shfl_xor_sync(0xFFFFFFFFu, pl, 1);
            pl += __shfl_xor_sync(0xFFFFFFFFu, pl, 2);
            pl += __shfl_xor_sync(0xFFFFFFFFu, pl, 4);
            float w = (e < n) ? __expf(pl) : 0.f;
            if (grp == 0) den += w;
            acc.x += w * cur.x; acc.y += w * cur.y;
            acc.z += w * cur.z; acc.w += w * cur.w;
        }
    }

    // fold erow groups: lanes {grp, grp+8, grp+16, grp+24} hold same channels
    acc.x += __shfl_xor_sync(0xFFFFFFFFu, acc.x, 8);
    acc.y += __shfl_xor_sync(0xFFFFFFFFu, acc.y, 8);
    acc.z += __shfl_xor_sync(0xFFFFFFFFu, acc.z, 8);
    acc.w += __shfl_xor_sync(0xFFFFFFFFu, acc.w, 8);
    acc.x += __shfl_xor_sync(0xFFFFFFFFu, acc.x, 16);
    acc.y += __shfl_xor_sync(0xFFFFFFFFu, acc.y, 16);
    acc.z += __shfl_xor_sync(0xFFFFFFFFu, acc.z, 16);
    acc.w += __shfl_xor_sync(0xFFFFFFFFu, acc.w, 16);
    den = warpSum(den);

    if (erow == 0) {
        float inv = 1.f / (den + 1e-16f);
        float4 b4 = *(const float4*)&b1[h * CH1 + c4];
        float4 o;
        o.x = (acc.x - den * xr4.x) * inv + b4.x;
        o.y = (acc.y - den * xr4.y) * inv + b4.y;
        o.z = (acc.z - den * xr4.z) * inv + b4.z;
        o.w = (acc.w - den * xr4.w) * inv + b4.w;
        o.x = (o.x > 0.f) ? o.x : (__expf(o.x) - 1.f);
        o.y = (o.y > 0.f) ? o.y : (__expf(o.y) - 1.f);
        o.z = (o.z > 0.f) ? o.z : (__expf(o.z) - 1.f);
        o.w = (o.w > 0.f) ? o.w : (__expf(o.w) - 1.f);
        *(float4*)&g_h1[d * F1 + h * CH1 + c4] = o;
    }
}

// ---------------------------------------------------------------------------
// Fused GAT layer 2: warp per node, lane covers channels c and c+32.
// 2-edge interleaved chains, no-max softmax.
// ---------------------------------------------------------------------------
__global__ void gat2_node_kernel(const float* __restrict__ att2, int nN) {
    int d = blockIdx.x * 4 + (threadIdx.x >> 5);
    if (d >= nN) return;
    int lane = threadIdx.x & 31;
    float a0 = att2[lane], a1 = att2[32 + lane];
    float xr0 = g_xr2[d * F2 + lane];
    float xr1 = g_xr2[d * F2 + 32 + lane];
    int beg = g_rowptr[d], end = g_rowptr[d + 1];

    float denA = 0.f, accA0 = 0.f, accA1 = 0.f;
    float denB = 0.f, accB0 = 0.f, accB1 = 0.f;

    int s0 = g_csrc[beg];
    float xa0 = g_xl2[s0 * F2 + lane];
    float xa1 = g_xl2[s0 * F2 + 32 + lane];
    float xb0 = 0.f, xb1 = 0.f;
    if (beg + 1 < end) {
        int s1 = g_csrc[beg + 1];
        xb0 = g_xl2[s1 * F2 + lane];
        xb1 = g_xl2[s1 * F2 + 32 + lane];
    }

    int j = beg;
    for (; j + 1 < end; j += 2) {
        float cA0 = xa0, cA1 = xa1, cB0 = xb0, cB1 = xb1;
        if (j + 2 < end) {
            int s = g_csrc[j + 2];
            xa0 = g_xl2[s * F2 + lane];
            xa1 = g_xl2[s * F2 + 32 + lane];
        }
        if (j + 3 < end) {
            int s = g_csrc[j + 3];
            xb0 = g_xl2[s * F2 + lane];
            xb1 = g_xl2[s * F2 + 32 + lane];
        }
        float pA = warpSum(leaky(cA0 + xr0) * a0 + leaky(cA1 + xr1) * a1);
        float pB = warpSum(leaky(cB0 + xr0) * a0 + leaky(cB1 + xr1) * a1);
        float wA = __expf(pA);
        denA += wA; accA0 += wA * cA0; accA1 += wA * cA1;
        float wB = __expf(pB);
        denB += wB; accB0 += wB * cB0; accB1 += wB * cB1;
    }
    if (j < end) {
        float pA = warpSum(leaky(xa0 + xr0) * a0 + leaky(xa1 + xr1) * a1);
        float wA = __expf(pA);
        denA += wA; accA0 += wA * xa0; accA1 += wA * xa1;
    }
    float inv = 1.f / (denA + denB + 1e-16f);
    g_h2[d * F2 + lane]      = (accA0 + accB0) * inv;
    g_h2[d * F2 + 32 + lane] = (accA1 + accB1) * inv;
}

// ---------------------------------------------------------------------------
// InstanceNorm stats: coalesced, warp-per-row-stripe, float atomics
// ---------------------------------------------------------------------------
__global__ void stats_kernel(int nN) {
    int gw = (blockIdx.x * blockDim.x + threadIdx.x) >> 5;
    int nw = (gridDim.x * blockDim.x) >> 5;
    int lane = threadIdx.x & 31;
    float s0 = 0.f, q0 = 0.f, s1 = 0.f, q1 = 0.f;
    for (int i = gw; i < nN; i += nw) {
        float v0 = g_h2[i * F2 + lane];
        float v1 = g_h2[i * F2 + 32 + lane];
        s0 += v0; q0 += v0 * v0;
        s1 += v1; q1 += v1 * v1;
    }
    atomicAdd(&g_fsum[lane], s0);
    atomicAdd(&g_fsq [lane], q0);
    atomicAdd(&g_fsum[32 + lane], s1);
    atomicAdd(&g_fsq [32 + lane], q1);
}

// ---------------------------------------------------------------------------
// Normalize + log_softmax (mean/rstd computed inline)
// ---------------------------------------------------------------------------
__global__ void finalize_kernel(const float* __restrict__ gamma,
                                const float* __restrict__ beta,
                                float* __restrict__ out, int nN) {
    int node = blockIdx.x * 4 + (threadIdx.x >> 5);
    if (node >= nN) return;
    int lane = threadIdx.x & 31;
    int c0 = lane, c1 = lane + 32;
    float invN = 1.f / (float)nN;
    float mean0 = g_fsum[c0] * invN;
    float mean1 = g_fsum[c1] * invN;
    float var0 = g_fsq[c0] * invN - mean0 * mean0;
    float var1 = g_fsq[c1] * invN - mean1 * mean1;
    float rstd0 = rsqrtf(var0 + 1e-5f);
    float rstd1 = rsqrtf(var1 + 1e-5f);
    float y0 = (g_h2[node * F2 + c0] - mean0) * rstd0 * gamma[c0] + beta[c0];
    float y1 = (g_h2[node * F2 + c1] - mean1) * rstd1 * gamma[c1] + beta[c1];
    out[node * F2 + c0] = y0;
    out[node * F2 + c1] = y1;
    float m = warpMax(fmaxf(y0, y1));
    float ssum = warpSum(expf(y0 - m) + expf(y1 - m));
    float lse = m + logf(ssum);
    float* out2 = out + (size_t)nN * F2;
    out2[node * F2 + c0] = y0 - lse;
    out2[node * F2 + c1] = y1 - lse;
}

// ---------------------------------------------------------------------------
// Launcher — CSR build forked onto side stream, overlapped with layer-1 GEMM
// ---------------------------------------------------------------------------
static cudaStream_t s_side = nullptr;
static cudaEvent_t  s_ev0 = nullptr, s_ev1 = nullptr;

extern "C" void kernel_launch(void* const* d_in, const int* in_sizes, int n_in,
                              void* d_out, int out_size) {
    const float* x     = (const float*)d_in[0];
    const float* Wl1   = (const float*)d_in[1];
    const float* Wr1   = (const float*)d_in[2];
    const float* att1  = (const float*)d_in[3];
    const float* b1    = (const float*)d_in[4];
    const float* Wl2   = (const float*)d_in[5];
    const float* Wr2   = (const float*)d_in[6];
    const float* att2  = (const float*)d_in[7];
    const float* gamma = (const float*)d_in[9];
    const float* beta  = (const float*)d_in[10];
    const int*   ei    = (const int*)d_in[11];

    int nN = in_sizes[0] / F0;
    int nE = in_sizes[11] / 2;
    int nET = nE + nN;
    const int* src = ei;
    const int* dst = ei + nE;

    if (s_side == nullptr) {
        cudaStreamCreateWithFlags(&s_side, cudaStreamNonBlocking);
        cudaEventCreateWithFlags(&s_ev0, cudaEventDisableTiming);
        cudaEventCreateWithFlags(&s_ev1, cudaEventDisableTiming);
    }

    float *xl1, *xr1, *h1, *xl2, *xr2;
    cudaGetSymbolAddress((void**)&xl1, g_xl1);
    cudaGetSymbolAddress((void**)&xr1, g_xr1);
    cudaGetSymbolAddress((void**)&h1,  g_h1);
    cudaGetSymbolAddress((void**)&xl2, g_xl2);
    cudaGetSymbolAddress((void**)&xr2, g_xr2);

    // Fork: CSR build on side stream
    cudaEventRecord(s_ev0, 0);
    cudaStreamWaitEvent(s_side, s_ev0, 0);
    zero_deg_kernel<<<(nN + 255) / 256, 256, 0, s_side>>>(nN);
    hist_kernel<<<(nET + 255) / 256, 256, 0, s_side>>>(dst, nE, nET);
    scan_kernel<<<1, 1024, 0, s_side>>>(nN);
    scatter_kernel<<<(nET + 255) / 256, 256, 0, s_side>>>(src, dst, nE, nET);
    cudaEventRecord(s_ev1, s_side);

    // Main: layer-1 GEMMs concurrent with CSR
    {
        dim3 grid(F1 / 64, (nN + 127) / 128, 2);
        mma_gemm2_kernel<<<grid, 256>>>(x, Wl1, Wr1, xl1, xr1, nN, F0, F1);
    }
    // Join
    cudaStreamWaitEvent(0, s_ev1, 0);

    gat1_node_kernel<<<nN, 256>>>(att1, b1);

    {
        dim3 grid(F2 / 64, (nN + 127) / 128, 2);
        mma_gemm2_kernel<<<grid, 256>>>(h1, Wl2, Wr2, xl2, xr2, nN, F1, F2);
    }
    gat2_node_kernel<<<(nN + 3) / 4, 128>>>(att2, nN);

    stats_kernel<<<64, 256>>>(nN);
    finalize_kernel<<<(nN + 3) / 4, 128>>>(gamma, beta, (float*)d_out, nN);
}

// round 11
// speedup vs baseline: 6.3858x; 1.1326x over previous
#include <cuda_runtime.h>
#include <math.h>

#define MAXN 20000
#define MAXE 320000
#define MAXET (MAXE + MAXN)
#define H1 8
#define CH1 32
#define F1 256
#define F0 128
#define F2 64

// ---------------------------------------------------------------------------
// Scratch
// ---------------------------------------------------------------------------
__device__ float g_xl1[MAXN * F1];
__device__ float g_xr1[MAXN * F1];
__device__ float g_h1 [MAXN * F1];
__device__ float g_xl2[MAXN * F2];
__device__ float g_xr2[MAXN * F2];
__device__ float g_h2 [MAXN * F2];

__device__ int g_deg[MAXN];
__device__ int g_rowptr[MAXN + 1];
__device__ int g_cursor[MAXN];
__device__ int g_csrc[MAXET];
__device__ int g_bsum[256];

__device__ float g_fsum[F2];
__device__ float g_fsq [F2];

// ---------------------------------------------------------------------------
// Helpers
// ---------------------------------------------------------------------------
__device__ __forceinline__ float warpSum(float v) {
    #pragma unroll
    for (int o = 16; o > 0; o >>= 1) v += __shfl_xor_sync(0xFFFFFFFFu, v, o);
    return v;
}
__device__ __forceinline__ float warpMax(float v) {
    #pragma unroll
    for (int o = 16; o > 0; o >>= 1) v = fmaxf(v, __shfl_xor_sync(0xFFFFFFFFu, v, o));
    return v;
}
__device__ __forceinline__ float f2tf32f(float x) {
    unsigned u;
    asm("cvt.rna.tf32.f32 %0, %1;" : "=r"(u) : "f"(x));
    return __uint_as_float(u);
}
__device__ __forceinline__ float leaky(float v) { return fmaxf(v, 0.2f * v); }

// ---------------------------------------------------------------------------
// CSR build (side stream, overlapped with layer-1 GEMM)
// ---------------------------------------------------------------------------
__global__ void zero_deg_kernel(int nN) {
    int i = blockIdx.x * blockDim.x + threadIdx.x;
    if (i < nN) g_deg[i] = 0;
    if (i < F2) { g_fsum[i] = 0.f; g_fsq[i] = 0.f; }
}

__global__ void hist_kernel(const int* __restrict__ dst, int nE, int nET) {
    int i = blockIdx.x * blockDim.x + threadIdx.x;
    if (i >= nET) return;
    int d = (i < nE) ? dst[i] : i - nE;
    atomicAdd(&g_deg[d], 1);
}

// Coalesced 3-phase scan.
// Phase 1: per-256-block sums.
__global__ void scan1_kernel(int nN) {
    int i = blockIdx.x * 256 + threadIdx.x;
    int v = (i < nN) ? g_deg[i] : 0;
    int lane = threadIdx.x & 31, w = threadIdx.x >> 5;
    #pragma unroll
    for (int o = 16; o > 0; o >>= 1) v += __shfl_xor_sync(0xFFFFFFFFu, v, o);
    __shared__ int ws[8];
    if (lane == 0) ws[w] = v;
    __syncthreads();
    if (threadIdx.x == 0) {
        int t = 0;
        #pragma unroll
        for (int j = 0; j < 8; j++) t += ws[j];
        g_bsum[blockIdx.x] = t;
    }
}

// Phase 2: single block scans the <=256 block sums (exclusive).
__global__ void scan2_kernel(int nb, int nN) {
    __shared__ int sh[256];
    int tid = threadIdx.x;
    int v = (tid < nb) ? g_bsum[tid] : 0;
    sh[tid] = v;
    __syncthreads();
    #pragma unroll
    for (int o = 1; o < 256; o <<= 1) {
        int t = (tid >= o) ? sh[tid - o] : 0;
        __syncthreads();
        sh[tid] += t;
        __syncthreads();
    }
    g_bsum[tid] = sh[tid] - v;        // exclusive block offset
    if (tid == 255) g_rowptr[nN] = sh[255];
}

// Phase 3: block-local exclusive scan + global offset, coalesced writes.
__global__ void scan3_kernel(int nN) {
    int tid = threadIdx.x;
    int i = blockIdx.x * 256 + tid;
    int v = (i < nN) ? g_deg[i] : 0;
    int lane = tid & 31, w = tid >> 5;
    int x = v;
    #pragma unroll
    for (int o = 1; o < 32; o <<= 1) {
        int t = __shfl_up_sync(0xFFFFFFFFu, x, o);
        if (lane >= o) x += t;
    }
    __shared__ int ws[8];
    if (lane == 31) ws[w] = x;
    __syncthreads();
    int woff = 0;
    for (int j = 0; j < w; j++) woff += ws[j];
    int excl = x - v + woff + g_bsum[blockIdx.x];
    if (i < nN) { g_rowptr[i] = excl; g_cursor[i] = excl; }
}

__global__ void scatter_kernel(const int* __restrict__ src,
                               const int* __restrict__ dst, int nE, int nET) {
    int i = blockIdx.x * blockDim.x + threadIdx.x;
    if (i >= nET) return;
    int s, d;
    if (i < nE) { s = src[i]; d = dst[i]; } else { s = d = i - nE; }
    int slot = atomicAdd(&g_cursor[d], 1);
    g_csrc[slot] = s;
}

// ---------------------------------------------------------------------------
// Pipelined TF32 GEMM: BM=128, BN=64, BK=16, 256 threads (8 warps, 4x2).
// ---------------------------------------------------------------------------
#define PADA 20
#define PADB 72
__global__ void __launch_bounds__(256, 2)
mma_gemm2_kernel(const float* __restrict__ Amat,
                 const float* __restrict__ Bl,
                 const float* __restrict__ Br,
                 float* __restrict__ outL,
                 float* __restrict__ outR,
                 int Mdim, int Kdim, int Ndim) {
    const float* Bmat = blockIdx.z ? Br : Bl;
    float*       Cmat = blockIdx.z ? outR : outL;
    __shared__ __align__(16) float As[2][128][PADA];
    __shared__ __align__(16) float Bs[2][16][PADB];
    int tid = threadIdx.x;
    int lane = tid & 31, warp = tid >> 5;
    int wm = warp >> 1, wn = warp & 1;
    int g = lane >> 2, tg = lane & 3;
    int row0 = blockIdx.y * 128, col0 = blockIdx.x * 64;

    int ar0 = tid >> 2, ac = (tid & 3) * 4;
    int br = tid >> 4, bc = (tid & 15) * 4;

    float4 ra[2], rb;

    float acc[2][4][4];
    #pragma unroll
    for (int i = 0; i < 2; i++)
        #pragma unroll
        for (int j = 0; j < 4; j++)
            #pragma unroll
            for (int k = 0; k < 4; k++) acc[i][j][k] = 0.f;

    int nit = Kdim / 16;

    #pragma unroll
    for (int i = 0; i < 2; i++) {
        int gr = row0 + ar0 + i * 64;
        ra[i] = (gr < Mdim) ? *(const float4*)&Amat[(size_t)gr * Kdim + ac]
                            : make_float4(0.f, 0.f, 0.f, 0.f);
    }
    rb = *(const float4*)&Bmat[(size_t)br * Ndim + col0 + bc];
    #pragma unroll
    for (int i = 0; i < 2; i++) {
        int r = ar0 + i * 64;
        As[0][r][ac + 0] = f2tf32f(ra[i].x);
        As[0][r][ac + 1] = f2tf32f(ra[i].y);
        As[0][r][ac + 2] = f2tf32f(ra[i].z);
        As[0][r][ac + 3] = f2tf32f(ra[i].w);
    }
    Bs[0][br][bc + 0] = f2tf32f(rb.x);
    Bs[0][br][bc + 1] = f2tf32f(rb.y);
    Bs[0][br][bc + 2] = f2tf32f(rb.z);
    Bs[0][br][bc + 3] = f2tf32f(rb.w);
    __syncthreads();

    for (int it = 0; it < nit; it++) {
        int k0n = (it + 1) * 16;
        bool more = (it + 1) < nit;
        if (more) {
            #pragma unroll
            for (int i = 0; i < 2; i++) {
                int gr = row0 + ar0 + i * 64;
                ra[i] = (gr < Mdim) ? *(const float4*)&Amat[(size_t)gr * Kdim + k0n + ac]
                                    : make_float4(0.f, 0.f, 0.f, 0.f);
            }
            rb = *(const float4*)&Bmat[(size_t)(k0n + br) * Ndim + col0 + bc];
        }
        int cb = it & 1;
        #pragma unroll
        for (int kk = 0; kk < 16; kk += 8) {
            unsigned a[2][4], b[4][2];
            #pragma unroll
            for (int mt = 0; mt < 2; mt++) {
                int r = wm * 32 + mt * 16;
                a[mt][0] = __float_as_uint(As[cb][r + g][kk + tg]);
                a[mt][1] = __float_as_uint(As[cb][r + g + 8][kk + tg]);
                a[mt][2] = __float_as_uint(As[cb][r + g][kk + tg + 4]);
                a[mt][3] = __float_as_uint(As[cb][r + g + 8][kk + tg + 4]);
            }
            #pragma unroll
            for (int nt = 0; nt < 4; nt++) {
                int c = wn * 32 + nt * 8 + g;
                b[nt][0] = __float_as_uint(Bs[cb][kk + tg][c]);
                b[nt][1] = __float_as_uint(Bs[cb][kk + tg + 4][c]);
            }
            #pragma unroll
            for (int mt = 0; mt < 2; mt++)
                #pragma unroll
                for (int nt = 0; nt < 4; nt++) {
                    asm volatile(
                        "mma.sync.aligned.m16n8k8.row.col.f32.tf32.tf32.f32 "
                        "{%0,%1,%2,%3}, {%4,%5,%6,%7}, {%8,%9}, {%0,%1,%2,%3};\n"
                        : "+f"(acc[mt][nt][0]), "+f"(acc[mt][nt][1]),
                          "+f"(acc[mt][nt][2]), "+f"(acc[mt][nt][3])
                        : "r"(a[mt][0]), "r"(a[mt][1]), "r"(a[mt][2]), "r"(a[mt][3]),
                          "r"(b[nt][0]), "r"(b[nt][1]));
                }
        }
        if (more) {
            __syncthreads();
            int sb = (it + 1) & 1;
            #pragma unroll
            for (int i = 0; i < 2; i++) {
                int r = ar0 + i * 64;
                As[sb][r][ac + 0] = f2tf32f(ra[i].x);
                As[sb][r][ac + 1] = f2tf32f(ra[i].y);
                As[sb][r][ac + 2] = f2tf32f(ra[i].z);
                As[sb][r][ac + 3] = f2tf32f(ra[i].w);
            }
            Bs[sb][br][bc + 0] = f2tf32f(rb.x);
            Bs[sb][br][bc + 1] = f2tf32f(rb.y);
            Bs[sb][br][bc + 2] = f2tf32f(rb.z);
            Bs[sb][br][bc + 3] = f2tf32f(rb.w);
            __syncthreads();
        }
    }
    #pragma unroll
    for (int mt = 0; mt < 2; mt++) {
        int rbase = row0 + wm * 32 + mt * 16;
        #pragma unroll
        for (int nt = 0; nt < 4; nt++) {
            int c = col0 + wn * 32 + nt * 8 + tg * 2;
            int r = rbase + g;
            if (r < Mdim) *(float2*)&Cmat[(size_t)r * Ndim + c] =
                make_float2(acc[mt][nt][0], acc[mt][nt][1]);
            r = rbase + g + 8;
            if (r < Mdim) *(float2*)&Cmat[(size_t)r * Ndim + c] =
                make_float2(acc[mt][nt][2], acc[mt][nt][3]);
        }
    }
}

// ---------------------------------------------------------------------------
// Fused GAT layer 1 — register-only (no shared memory, no syncs).
// ---------------------------------------------------------------------------
__global__ void gat1_node_kernel(const float* __restrict__ att1,
                                 const float* __restrict__ b1) {
    int d = blockIdx.x;
    int h = threadIdx.x >> 5, lane = threadIdx.x & 31;
    int grp = lane & 7, erow = lane >> 3;
    int c4 = grp * 4;

    float4 at4 = *(const float4*)&att1[h * CH1 + c4];
    float4 xr4 = *(const float4*)&g_xr1[d * F1 + h * CH1 + c4];
    const float* xlh = g_xl1 + h * CH1;

    int beg = g_rowptr[d], end = g_rowptr[d + 1];
    float den = 0.f;
    float4 acc = make_float4(0.f, 0.f, 0.f, 0.f);

    for (int t = beg; t < end; t += 32) {
        int n = end - t; if (n > 32) n = 32;
        int idx = t + lane;
        int sidx = g_csrc[(idx < end) ? idx : beg];
        int np = (n + 3) >> 2;

        int se = __shfl_sync(0xFFFFFFFFu, sidx, erow);
        float4 v = *(const float4*)&xlh[(size_t)se * F1 + c4];

        for (int p = 0; p < np; p++) {
            float4 cur = v;
            if (p + 1 < np) {
                int se2 = __shfl_sync(0xFFFFFFFFu, sidx, (p + 1) * 4 + erow);
                v = *(const float4*)&xlh[(size_t)se2 * F1 + c4];
            }
            int e = p * 4 + erow;
            cur.x += xr4.x; cur.y += xr4.y; cur.z += xr4.z; cur.w += xr4.w;
            float pl = at4.x * leaky(cur.x) + at4.y * leaky(cur.y)
                     + at4.z * leaky(cur.z) + at4.w * leaky(cur.w);
            pl += __shfl_xor_sync(0xFFFFFFFFu, pl, 1);
            pl += __shfl_xor_sync(0xFFFFFFFFu, pl, 2);
            pl += __shfl_xor_sync(0xFFFFFFFFu, pl, 4);
            float w = (e < n) ? __expf(pl) : 0.f;
            if (grp == 0) den += w;
            acc.x += w * cur.x; acc.y += w * cur.y;
            acc.z += w * cur.z; acc.w += w * cur.w;
        }
    }

    acc.x += __shfl_xor_sync(0xFFFFFFFFu, acc.x, 8);
    acc.y += __shfl_xor_sync(0xFFFFFFFFu, acc.y, 8);
    acc.z += __shfl_xor_sync(0xFFFFFFFFu, acc.z, 8);
    acc.w += __shfl_xor_sync(0xFFFFFFFFu, acc.w, 8);
    acc.x += __shfl_xor_sync(0xFFFFFFFFu, acc.x, 16);
    acc.y += __shfl_xor_sync(0xFFFFFFFFu, acc.y, 16);
    acc.z += __shfl_xor_sync(0xFFFFFFFFu, acc.z, 16);
    acc.w += __shfl_xor_sync(0xFFFFFFFFu, acc.w, 16);
    den = warpSum(den);

    if (erow == 0) {
        float inv = 1.f / (den + 1e-16f);
        float4 b4 = *(const float4*)&b1[h * CH1 + c4];
        float4 o;
        o.x = (acc.x - den * xr4.x) * inv + b4.x;
        o.y = (acc.y - den * xr4.y) * inv + b4.y;
        o.z = (acc.z - den * xr4.z) * inv + b4.z;
        o.w = (acc.w - den * xr4.w) * inv + b4.w;
        o.x = (o.x > 0.f) ? o.x : (__expf(o.x) - 1.f);
        o.y = (o.y > 0.f) ? o.y : (__expf(o.y) - 1.f);
        o.z = (o.z > 0.f) ? o.z : (__expf(o.z) - 1.f);
        o.w = (o.w > 0.f) ? o.w : (__expf(o.w) - 1.f);
        *(float4*)&g_h1[d * F1 + h * CH1 + c4] = o;
    }
}

// ---------------------------------------------------------------------------
// Fused GAT layer 2 — register-only, same scheme as gat1.
// Warp per node. grp = lane&15 owns channels 4*grp..4*grp+3 (16x16B = full
// 256B row); erow = lane>>4 selects 1 of 2 edges per pass.
// ---------------------------------------------------------------------------
__global__ void gat2_node_kernel(const float* __restrict__ att2, int nN) {
    int d = blockIdx.x * 4 + (threadIdx.x >> 5);
    if (d >= nN) return;
    int lane = threadIdx.x & 31;
    int grp = lane & 15, erow = lane >> 4;
    int c4 = grp * 4;

    float4 at4 = *(const float4*)&att2[c4];
    float4 xr4 = *(const float4*)&g_xr2[d * F2 + c4];

    int beg = g_rowptr[d], end = g_rowptr[d + 1];
    float den = 0.f;
    float4 acc = make_float4(0.f, 0.f, 0.f, 0.f);

    for (int t = beg; t < end; t += 32) {
        int n = end - t; if (n > 32) n = 32;
        int idx = t + lane;
        int sidx = g_csrc[(idx < end) ? idx : beg];
        int np = (n + 1) >> 1;

        int se = __shfl_sync(0xFFFFFFFFu, sidx, erow);
        float4 v = *(const float4*)&g_xl2[(size_t)se * F2 + c4];

        for (int p = 0; p < np; p++) {
            float4 cur = v;
            if (p + 1 < np) {
                int se2 = __shfl_sync(0xFFFFFFFFu, sidx, (p + 1) * 2 + erow);
                v = *(const float4*)&g_xl2[(size_t)se2 * F2 + c4];
            }
            int e = p * 2 + erow;
            cur.x += xr4.x; cur.y += xr4.y; cur.z += xr4.z; cur.w += xr4.w;
            float pl = at4.x * leaky(cur.x) + at4.y * leaky(cur.y)
                     + at4.z * leaky(cur.z) + at4.w * leaky(cur.w);
            pl += __shfl_xor_sync(0xFFFFFFFFu, pl, 1);
            pl += __shfl_xor_sync(0xFFFFFFFFu, pl, 2);
            pl += __shfl_xor_sync(0xFFFFFFFFu, pl, 4);
            pl += __shfl_xor_sync(0xFFFFFFFFu, pl, 8);
            float w = (e < n) ? __expf(pl) : 0.f;
            if (grp == 0) den += w;
            acc.x += w * cur.x; acc.y += w * cur.y;
            acc.z += w * cur.z; acc.w += w * cur.w;
        }
    }

    acc.x += __shfl_xor_sync(0xFFFFFFFFu, acc.x, 16);
    acc.y += __shfl_xor_sync(0xFFFFFFFFu, acc.y, 16);
    acc.z += __shfl_xor_sync(0xFFFFFFFFu, acc.z, 16);
    acc.w += __shfl_xor_sync(0xFFFFFFFFu, acc.w, 16);
    den = warpSum(den);

    if (erow == 0) {
        float inv = 1.f / (den + 1e-16f);
        float4 o;
        o.x = (acc.x - den * xr4.x) * inv;
        o.y = (acc.y - den * xr4.y) * inv;
        o.z = (acc.z - den * xr4.z) * inv;
        o.w = (acc.w - den * xr4.w) * inv;
        *(float4*)&g_h2[d * F2 + c4] = o;   // b2 cancels in InstanceNorm
    }
}

// ---------------------------------------------------------------------------
// InstanceNorm stats: coalesced, warp-per-row-stripe, float atomics
// ---------------------------------------------------------------------------
__global__ void stats_kernel(int nN) {
    int gw = (blockIdx.x * blockDim.x + threadIdx.x) >> 5;
    int nw = (gridDim.x * blockDim.x) >> 5;
    int lane = threadIdx.x & 31;
    float s0 = 0.f, q0 = 0.f, s1 = 0.f, q1 = 0.f;
    for (int i = gw; i < nN; i += nw) {
        float v0 = g_h2[i * F2 + lane];
        float v1 = g_h2[i * F2 + 32 + lane];
        s0 += v0; q0 += v0 * v0;
        s1 += v1; q1 += v1 * v1;
    }
    atomicAdd(&g_fsum[lane], s0);
    atomicAdd(&g_fsq [lane], q0);
    atomicAdd(&g_fsum[32 + lane], s1);
    atomicAdd(&g_fsq [32 + lane], q1);
}

// ---------------------------------------------------------------------------
// Normalize + log_softmax (mean/rstd computed inline)
// ---------------------------------------------------------------------------
__global__ void finalize_kernel(const float* __restrict__ gamma,
                                const float* __restrict__ beta,
                                float* __restrict__ out, int nN) {
    int node = blockIdx.x * 4 + (threadIdx.x >> 5);
    if (node >= nN) return;
    int lane = threadIdx.x & 31;
    int c0 = lane, c1 = lane + 32;
    float invN = 1.f / (float)nN;
    float mean0 = g_fsum[c0] * invN;
    float mean1 = g_fsum[c1] * invN;
    float var0 = g_fsq[c0] * invN - mean0 * mean0;
    float var1 = g_fsq[c1] * invN - mean1 * mean1;
    float rstd0 = rsqrtf(var0 + 1e-5f);
    float rstd1 = rsqrtf(var1 + 1e-5f);
    float y0 = (g_h2[node * F2 + c0] - mean0) * rstd0 * gamma[c0] + beta[c0];
    float y1 = (g_h2[node * F2 + c1] - mean1) * rstd1 * gamma[c1] + beta[c1];
    out[node * F2 + c0] = y0;
    out[node * F2 + c1] = y1;
    float m = warpMax(fmaxf(y0, y1));
    float ssum = warpSum(expf(y0 - m) + expf(y1 - m));
    float lse = m + logf(ssum);
    float* out2 = out + (size_t)nN * F2;
    out2[node * F2 + c0] = y0 - lse;
    out2[node * F2 + c1] = y1 - lse;
}

// ---------------------------------------------------------------------------
// Launcher — CSR build forked onto side stream, overlapped with layer-1 GEMM
// ---------------------------------------------------------------------------
static cudaStream_t s_side = nullptr;
static cudaEvent_t  s_ev0 = nullptr, s_ev1 = nullptr;

extern "C" void kernel_launch(void* const* d_in, const int* in_sizes, int n_in,
                              void* d_out, int out_size) {
    const float* x     = (const float*)d_in[0];
    const float* Wl1   = (const float*)d_in[1];
    const float* Wr1   = (const float*)d_in[2];
    const float* att1  = (const float*)d_in[3];
    const float* b1    = (const float*)d_in[4];
    const float* Wl2   = (const float*)d_in[5];
    const float* Wr2   = (const float*)d_in[6];
    const float* att2  = (const float*)d_in[7];
    const float* gamma = (const float*)d_in[9];
    const float* beta  = (const float*)d_in[10];
    const int*   ei    = (const int*)d_in[11];

    int nN = in_sizes[0] / F0;
    int nE = in_sizes[11] / 2;
    int nET = nE + nN;
    int nb = (nN + 255) / 256;
    const int* src = ei;
    const int* dst = ei + nE;

    if (s_side == nullptr) {
        cudaStreamCreateWithFlags(&s_side, cudaStreamNonBlocking);
        cudaEventCreateWithFlags(&s_ev0, cudaEventDisableTiming);
        cudaEventCreateWithFlags(&s_ev1, cudaEventDisableTiming);
    }

    float *xl1, *xr1, *h1, *xl2, *xr2;
    cudaGetSymbolAddress((void**)&xl1, g_xl1);
    cudaGetSymbolAddress((void**)&xr1, g_xr1);
    cudaGetSymbolAddress((void**)&h1,  g_h1);
    cudaGetSymbolAddress((void**)&xl2, g_xl2);
    cudaGetSymbolAddress((void**)&xr2, g_xr2);

    // Fork: CSR build on side stream
    cudaEventRecord(s_ev0, 0);
    cudaStreamWaitEvent(s_side, s_ev0, 0);
    zero_deg_kernel<<<(nN + 255) / 256, 256, 0, s_side>>>(nN);
    hist_kernel<<<(nET + 255) / 256, 256, 0, s_side>>>(dst, nE, nET);
    scan1_kernel<<<nb, 256, 0, s_side>>>(nN);
    scan2_kernel<<<1, 256, 0, s_side>>>(nb, nN);
    scan3_kernel<<<nb, 256, 0, s_side>>>(nN);
    scatter_kernel<<<(nET + 255) / 256, 256, 0, s_side>>>(src, dst, nE, nET);
    cudaEventRecord(s_ev1, s_side);

    // Main: layer-1 GEMMs concurrent with CSR
    {
        dim3 grid(F1 / 64, (nN + 127) / 128, 2);
        mma_gemm2_kernel<<<grid, 256>>>(x, Wl1, Wr1, xl1, xr1, nN, F0, F1);
    }
    // Join
    cudaStreamWaitEvent(0, s_ev1, 0);

    gat1_node_kernel<<<nN, 256>>>(att1, b1);

    {
        dim3 grid(F2 / 64, (nN + 127) / 128, 2);
        mma_gemm2_kernel<<<grid, 256>>>(h1, Wl2, Wr2, xl2, xr2, nN, F1, F2);
    }
    gat2_node_kernel<<<(nN + 3) / 4, 128>>>(att2, nN);

    stats_kernel<<<64, 256>>>(nN);
    finalize_kernel<<<(nN + 3) / 4, 128>>>(gamma, beta, (float*)d_out, nN);
}